// round 9
// baseline (speedup 1.0000x reference)
#include <cuda_runtime.h>
#include <cuda_bf16.h>
#include <math.h>
#include <cstdint>

// Problem dims
#define BB 512
#define TN 300
#define DD 200
#define HH 128
#define GG 512   // 4*H
#define MM (TN*BB)      // 153600 rows
#define KP 256          // padded K per segment

// ---------------- static device scratch ----------------
__device__ float g_xpA[(size_t)TN * BB * GG];
__device__ float g_xpB[(size_t)TN * BB * GG];
__device__ float g_f1 [(size_t)TN * BB * HH];
__device__ float g_r1 [(size_t)TN * BB * HH];
__device__ float4 g_whhT4[4 * HH * HH];          // [mat][k][h] -> (g0,g1,g2,g3)
__device__ float g_wl1T[456 * HH];
__device__ float g_pooled[BB * HH];
__device__ __nv_bfloat16 g_Ahi[(size_t)MM * KP];
__device__ __nv_bfloat16 g_Alo[(size_t)MM * KP];
__device__ __nv_bfloat16 g_W[4 * 2 * GG * KP];   // [proj][hi/lo][512][256]

__device__ __forceinline__ void atomicMaxF(float* addr, float v) {
    if (v >= 0.f) atomicMax((int*)addr, __float_as_int(v));
    else          atomicMin((unsigned int*)addr, __float_as_uint(v));
}

// ================= PTX helpers =================
__device__ __forceinline__ uint32_t smem_u32(const void* p) {
    uint32_t addr;
    asm("{ .reg .u64 tmp; cvta.to.shared.u64 tmp, %1; cvt.u32.u64 %0, tmp; }"
        : "=r"(addr) : "l"(p));
    return addr;
}
#define CP_ASYNC16(dst, src) \
    asm volatile("cp.async.ca.shared.global [%0], [%1], 16;" :: "r"(dst), "l"(src))
#define CP_COMMIT() asm volatile("cp.async.commit_group;" ::: "memory")
#define CP_WAIT1()  asm volatile("cp.async.wait_group 1;" ::: "memory")
#define CP_WAIT0()  asm volatile("cp.async.wait_group 0;" ::: "memory")

__device__ __forceinline__ void ldsm_x4(uint32_t& r0, uint32_t& r1, uint32_t& r2, uint32_t& r3,
                                        uint32_t addr) {
    asm volatile("ldmatrix.sync.aligned.m8n8.x4.shared.b16 {%0,%1,%2,%3}, [%4];"
        : "=r"(r0), "=r"(r1), "=r"(r2), "=r"(r3) : "r"(addr));
}
__device__ __forceinline__ void mma16816(float* d, const uint32_t* a, uint32_t b0, uint32_t b1) {
    asm volatile(
        "mma.sync.aligned.m16n8k16.row.col.f32.bf16.bf16.f32 "
        "{%0,%1,%2,%3}, {%4,%5,%6,%7}, {%8,%9}, {%0,%1,%2,%3};"
        : "+f"(d[0]), "+f"(d[1]), "+f"(d[2]), "+f"(d[3])
        : "r"(a[0]), "r"(a[1]), "r"(a[2]), "r"(a[3]), "r"(b0), "r"(b1));
}

// Packed fp32 pair (FFMA2) helpers
typedef unsigned long long u64t;
__device__ __forceinline__ u64t pack2(float a, float b) {
    u64t r; asm("mov.b64 %0, {%1,%2};" : "=l"(r) : "f"(a), "f"(b)); return r;
}
__device__ __forceinline__ void unpack2(u64t v, float& a, float& b) {
    asm("mov.b64 {%0,%1}, %2;" : "=f"(a), "=f"(b) : "l"(v));
}
__device__ __forceinline__ u64t fma2(u64t a, u64t b, u64t c) {
    u64t d; asm("fma.rn.f32x2 %0, %1, %2, %3;" : "=l"(d) : "l"(a), "l"(b), "l"(c)); return d;
}
__device__ __forceinline__ u64t add2(u64t a, u64t b) {
    u64t d; asm("add.rn.f32x2 %0, %1, %2;" : "=l"(d) : "l"(a), "l"(b)); return d;
}

// Fast activations (errors ~1e-5, budget 1e-3)
__device__ __forceinline__ float tanha(float x) {
    float y; asm("tanh.approx.f32 %0, %1;" : "=f"(y) : "f"(x)); return y;
}
__device__ __forceinline__ float sigf(float x) {
    float e; asm("ex2.approx.f32 %0, %1;" : "=f"(e) : "f"(-1.4426950408889634f * x));
    float r; asm("rcp.approx.f32 %0, %1;" : "=f"(r) : "f"(1.f + e));
    return r;
}

// ---------------- fused prep: whhT4 (x4), wl1T, pooled init ----------------
__global__ void prep_kernel(const float* __restrict__ w0, const float* __restrict__ w1,
                            const float* __restrict__ w2, const float* __restrict__ w3,
                            const float* __restrict__ wl1,
                            float4* __restrict__ whhT4, float* __restrict__ wl1T,
                            float* __restrict__ pooled) {
    int idx = blockIdx.x * blockDim.x + threadIdx.x;
    if (idx < 4 * HH * HH) {
        int mat = idx >> 14, rem = idx & 16383;
        int k = rem >> 7, h = rem & 127;
        const float* w = (mat == 0) ? w0 : (mat == 1) ? w1 : (mat == 2) ? w2 : w3;
        whhT4[idx] = make_float4(w[(0   + h) * HH + k], w[(128 + h) * HH + k],
                                 w[(256 + h) * HH + k], w[(384 + h) * HH + k]);
    }
    if (idx < 456 * HH) {
        int f = idx >> 7, o = idx & 127;
        wl1T[idx] = wl1[o * 456 + f];
    }
    if (idx < BB * HH) pooled[idx] = -2.0f;
}

// ---------------- fp32 -> bf16 hi/lo conversions ----------------
__global__ void conv_bx_kernel(const float* __restrict__ bx,
                               __nv_bfloat16* __restrict__ hi, __nv_bfloat16* __restrict__ lo) {
    size_t idx = (size_t)blockIdx.x * blockDim.x + threadIdx.x;
    if (idx >= (size_t)MM * KP) return;
    int m = (int)(idx >> 8), k = (int)(idx & 255);
    int t = m >> 9, b = m & 511;
    float v = (k < DD) ? bx[(size_t)b * TN * DD + (size_t)t * DD + k] : 0.f;
    __nv_bfloat16 h = __float2bfloat16(v);
    hi[idx] = h;
    lo[idx] = __float2bfloat16(v - __bfloat162float(h));
}
// all 4 weights in one kernel: out layout [proj][hi/lo][512][256]
__global__ void conv_w_all(const float* __restrict__ w0, const float* __restrict__ w1,
                           const float* __restrict__ w2, const float* __restrict__ w3,
                           __nv_bfloat16* __restrict__ out) {
    int idx = blockIdx.x * blockDim.x + threadIdx.x;
    if (idx >= 4 * GG * KP) return;
    int p = idx / (GG * KP), rem = idx % (GG * KP);
    int n = rem >> 8, k = rem & 255;
    const float* w = (p == 0) ? w0 : (p == 1) ? w1 : (p == 2) ? w2 : w3;
    int K = (p < 2) ? DD : 2 * HH;
    float v = (k < K) ? w[(size_t)n * K + k] : 0.f;
    __nv_bfloat16 h = __float2bfloat16(v);
    out[(size_t)(2 * p) * GG * KP + rem] = h;
    out[(size_t)(2 * p + 1) * GG * KP + rem] = __float2bfloat16(v - __bfloat162float(h));
}

// ---------------- HMMA projection GEMM ----------------
#define SROW 144
#define TILE_B (128 * SROW)
#define SMEM_PROJ (4 * TILE_B)
__global__ __launch_bounds__(256) void proj_mma(
    const __nv_bfloat16* __restrict__ Ahi, const __nv_bfloat16* __restrict__ Alo,
    const __nv_bfloat16* __restrict__ Whi, const __nv_bfloat16* __restrict__ Wlo,
    const float* __restrict__ b1, const float* __restrict__ b2,
    float* __restrict__ C) {
    extern __shared__ __align__(16) unsigned char dsm[];
    __shared__ float bias[128];
    int tid = threadIdx.x, lane = tid & 31, wid = tid >> 5;
    int wm = wid & 3, wn = wid >> 2;
    int m0 = blockIdx.y * 128, n0 = blockIdx.x * 128;
    if (tid < 128) bias[tid] = b1[n0 + tid] + b2[n0 + tid];

    uint32_t sa0 = smem_u32(dsm);
    uint32_t sb0 = sa0 + 2 * TILE_B;
    const __nv_bfloat16* Asegs[3] = { Ahi, Ahi, Alo };
    const __nv_bfloat16* Wsegs[3] = { Whi, Wlo, Whi };
    const int total = 12;

    auto load_chunk = [&](int c, int buf) {
        int seg = c >> 2;
        int ko = (c & 3) * 64;
        const __nv_bfloat16* As = Asegs[seg] + (size_t)m0 * KP + ko;
        const __nv_bfloat16* Ws = Wsegs[seg] + (size_t)n0 * KP + ko;
#pragma unroll
        for (int i = 0; i < 4; i++) {
            int idx = tid + i * 256;
            int row = idx >> 3, w = idx & 7;
            CP_ASYNC16(sa0 + buf * TILE_B + row * SROW + w * 16,
                       As + (size_t)row * KP + w * 8);
            CP_ASYNC16(sb0 + buf * TILE_B + row * SROW + w * 16,
                       Ws + (size_t)row * KP + w * 8);
        }
        CP_COMMIT();
    };

    float acc[2][8][4] = {};
    load_chunk(0, 0);
    load_chunk(1, 1);

    for (int c = 0; c < total; c++) {
        int buf = c & 1;
        if (c + 1 < total) CP_WAIT1(); else CP_WAIT0();
        __syncthreads();
        uint32_t ab = sa0 + buf * TILE_B;
        uint32_t bb = sb0 + buf * TILE_B;
#pragma unroll
        for (int ks = 0; ks < 4; ks++) {
            uint32_t a[2][4], b[4][4];
#pragma unroll
            for (int mt = 0; mt < 2; mt++) {
                uint32_t addr = ab + (uint32_t)(wm * 32 + mt * 16 + (lane & 15)) * SROW
                                   + (uint32_t)(ks * 16 + ((lane & 16) ? 8 : 0)) * 2;
                ldsm_x4(a[mt][0], a[mt][1], a[mt][2], a[mt][3], addr);
            }
#pragma unroll
            for (int np = 0; np < 4; np++) {
                uint32_t addr = bb + (uint32_t)(wn * 64 + np * 16 + (lane & 7) + ((lane & 16) ? 8 : 0)) * SROW
                                   + (uint32_t)(ks * 16 + ((lane & 8) ? 8 : 0)) * 2;
                ldsm_x4(b[np][0], b[np][1], b[np][2], b[np][3], addr);
            }
#pragma unroll
            for (int mt = 0; mt < 2; mt++)
#pragma unroll
                for (int nt = 0; nt < 8; nt++)
                    mma16816(acc[mt][nt], a[mt], b[nt >> 1][(nt & 1) * 2],
                             b[nt >> 1][(nt & 1) * 2 + 1]);
        }
        __syncthreads();
        if (c + 2 < total) load_chunk(c + 2, buf);
    }

#pragma unroll
    for (int mt = 0; mt < 2; mt++)
#pragma unroll
        for (int nt = 0; nt < 8; nt++) {
            int row  = m0 + wm * 32 + mt * 16 + (lane >> 2);
            int colL = wn * 64 + nt * 8 + (lane & 3) * 2;
            int col  = n0 + colL;
            float2 v0 = { acc[mt][nt][0] + bias[colL], acc[mt][nt][1] + bias[colL + 1] };
            float2 v1 = { acc[mt][nt][2] + bias[colL], acc[mt][nt][3] + bias[colL + 1] };
            *(float2*)(C + (size_t)row * 512 + col) = v0;
            *(float2*)(C + (size_t)(row + 8) * 512 + col) = v1;
        }
}

// ---------------- fused bidirectional LSTM recurrence (FFMA2, k-split, 512 thr) ----------------
// grid 128 = 2 dirs x 64 slices (8 rows). thread = (hcol, kh, rh):
//   hcol = tid&127 ; sub = tid>>7 ; kh = sub&1 (k in [kh*64,kh*64+64)) ; rh = sub>>1 (rows rh*4..+3)
// mode 0: write float out.  mode 1: write bf16 hi/lo split at column dir*128 (stride KP).
__global__ __launch_bounds__(512) void lstm_kernel(
    const float* __restrict__ xpF, const float* __restrict__ xpB,
    const float4* __restrict__ whhT4F, const float4* __restrict__ whhT4B,
    const float* __restrict__ hf,
    float* __restrict__ outF, float* __restrict__ outB, int outStride,
    __nv_bfloat16* __restrict__ ohi, __nv_bfloat16* __restrict__ olo, int mode) {
    __shared__ u64t hsh[2][8][HH];   // packed {h,h}
    __shared__ u64t red[2][8][HH];   // [rh][gate][hcol]
    int dir = blockIdx.x & 1;
    int rb = (blockIdx.x >> 1) * 8;
    const float*  xp  = dir ? xpB    : xpF;
    const float4* wT4 = dir ? whhT4B : whhT4F;
    float*        out = dir ? outB   : outF;
    int tid = threadIdx.x;
    int hcol = tid & 127;
    int sub  = tid >> 7;
    int kh   = sub & 1;
    int rh   = sub >> 1;
    int r0   = rh * 4;
    int kbase = kh * 64;
    float hfv = hf[hcol];
    float c[4];
    if (kh == 0) {
#pragma unroll
        for (int r = 0; r < 4; r++) { c[r] = hfv; hsh[0][r0 + r][hcol] = pack2(hfv, hfv); }
    }
    __syncthreads();

    const float4* wcol = wT4 + (size_t)kbase * HH + hcol;

    for (int t = 0; t < TN; t++) {
        int tef = dir ? (TN - 1 - t) : t;
        int cur = t & 1;
        // xp loads early (kh==0 only) — DRAM latency hidden under the k-loop
        float xr[4][4];
        if (kh == 0) {
            size_t rowbase = ((size_t)tef * BB + rb + r0) * GG + hcol;
#pragma unroll
            for (int r = 0; r < 4; r++) {
                const float* p = xp + rowbase + (size_t)r * GG;
                xr[r][0] = p[0];   xr[r][1] = p[128];
                xr[r][2] = p[256]; xr[r][3] = p[384];
            }
        }
        u64t a01[4] = {0ull, 0ull, 0ull, 0ull};
        u64t a23[4] = {0ull, 0ull, 0ull, 0ull};
        const float4* wp = wcol;
        float4 wc[8];
#pragma unroll
        for (int j = 0; j < 8; j++) wc[j] = wp[j * HH];
#pragma unroll
        for (int kc = 0; kc < 64; kc += 8) {
            float4 wn[8];
            if (kc + 8 < 64) {
#pragma unroll
                for (int j = 0; j < 8; j++) wn[j] = wp[(kc + 8 + j) * HH];
            }
#pragma unroll
            for (int j = 0; j < 8; j++) {
                int k = kbase + kc + j;
                u64t w01 = pack2(wc[j].x, wc[j].y);
                u64t w23 = pack2(wc[j].z, wc[j].w);
#pragma unroll
                for (int r = 0; r < 4; r++) {
                    u64t h2 = hsh[cur][r0 + r][k];
                    a01[r] = fma2(h2, w01, a01[r]);
                    a23[r] = fma2(h2, w23, a23[r]);
                }
            }
            if (kc + 8 < 64) {
#pragma unroll
                for (int j = 0; j < 8; j++) wc[j] = wn[j];
            }
        }
        if (kh == 1) {
#pragma unroll
            for (int r = 0; r < 4; r++) {
                red[rh][r][hcol]     = a01[r];
                red[rh][4 + r][hcol] = a23[r];
            }
        }
        __syncthreads();
        if (kh == 0) {
#pragma unroll
            for (int r = 0; r < 4; r++) {
                u64t p01 = add2(a01[r], red[rh][r][hcol]);
                u64t p23 = add2(a23[r], red[rh][4 + r][hcol]);
                float gi, gf_, gc, go;
                unpack2(p01, gi, gf_);
                unpack2(p23, gc, go);
                gi  += xr[r][0]; gf_ += xr[r][1];
                gc  += xr[r][2]; go  += xr[r][3];
                float ig = sigf(gi), fg = sigf(gf_);
                float cc = tanha(gc), og = sigf(go);
                float cv = fg * c[r] + ig * cc;
                c[r] = cv;
                float hv = og * tanha(cv);
                hsh[cur ^ 1][r0 + r][hcol] = pack2(hv, hv);
                size_t row = (size_t)tef * BB + rb + r0 + r;
                if (mode == 0) {
                    out[row * outStride + hcol] = hv;
                } else {
                    size_t o = row * KP + dir * 128 + hcol;
                    __nv_bfloat16 hh = __float2bfloat16(hv);
                    ohi[o] = hh;
                    olo[o] = __float2bfloat16(hv - __bfloat162float(hh));
                }
            }
        }
        __syncthreads();
    }
}

// ---------------- classifier: h = tanh(data @ w_l1^T), max over t ----------------
#define CTT 16
__global__ __launch_bounds__(256) void cls_kernel(
    const float* __restrict__ f1, const float* __restrict__ r1,
    const float* __restrict__ bx, const float* __restrict__ hf,
    const float* __restrict__ wl1T, float* __restrict__ pooled) {
    __shared__ float ds[CTT][456];
    int b = blockIdx.x;
    int tile = blockIdx.y;
    int tid = threadIdx.x;
    for (int idx = tid; idx < CTT * 456; idx += 256) {
        int tt = idx / 456, f = idx % 456;
        int t = tile * CTT + tt;
        float v = 0.f;
        if (t < TN) {
            if (f < 128) {
                v = (t == 0) ? hf[f] : f1[((size_t)t * BB + b) * HH + f];
            } else if (f < 328) {
                v = bx[(size_t)b * TN * DD + (size_t)t * DD + (f - 128)];
            } else {
                int j = f - 328;
                v = (t == TN - 1) ? hf[j] : r1[((size_t)(TN - 2 - t) * BB + b) * HH + j];
            }
        }
        ds[tt][f] = v;
    }
    __syncthreads();

    int o2 = (tid & 63) * 2;
    int tsub = tid >> 6;
    float acc[4][2];
#pragma unroll
    for (int q = 0; q < 4; q++) { acc[q][0] = 0.f; acc[q][1] = 0.f; }
    for (int f = 0; f < 456; f++) {
        float2 w = *(const float2*)(wl1T + f * HH + o2);
#pragma unroll
        for (int q = 0; q < 4; q++) {
            float dv = ds[tsub + q * 4][f];
            acc[q][0] += dv * w.x;
            acc[q][1] += dv * w.y;
        }
    }
    float m0v = -2.f, m1v = -2.f;
#pragma unroll
    for (int q = 0; q < 4; q++) {
        int t = tile * CTT + tsub + q * 4;
        if (t < TN) {
            m0v = fmaxf(m0v, tanha(acc[q][0]));
            m1v = fmaxf(m1v, tanha(acc[q][1]));
        }
    }
    atomicMaxF(&pooled[b * HH + o2],     m0v);
    atomicMaxF(&pooled[b * HH + o2 + 1], m1v);
}

// ---------------- final head ----------------
__global__ void out_kernel(const float* __restrict__ pooled,
                           const float* __restrict__ wl2, const float* __restrict__ bl2,
                           const int* __restrict__ by, float* __restrict__ outb,
                           int out_size) {
    __shared__ float sh[128];
    int b = blockIdx.x, tid = threadIdx.x;
    float p = pooled[b * 128 + tid];
    for (int o = 0; o < 4; o++) {
        float v = p * wl2[o * 128 + tid];
        sh[tid] = v;
        __syncthreads();
        if (tid < 64) sh[tid] += sh[tid + 64];
        __syncthreads();
        if (tid < 32) {
            float s = sh[tid] + sh[tid + 32];
            for (int off = 16; off; off >>= 1) s += __shfl_down_sync(0xffffffffu, s, off);
            if (tid == 0) outb[b * 4 + o] = s + bl2[o];
        }
        __syncthreads();
    }
    if (tid == 0 && out_size >= BB * 4 + BB) outb[BB * 4 + b] = (float)by[b];
}

// ---------------- launch ----------------
extern "C" void kernel_launch(void* const* d_in, const int* in_sizes, int n_in,
                              void* d_out, int out_size) {
    const float* bx       = (const float*)d_in[0];
    const int*   by       = (const int*)  d_in[1];
    const float* hf       = (const float*)d_in[2];
    const float* w_ih[4]  = { (const float*)d_in[3],  (const float*)d_in[7],
                              (const float*)d_in[11], (const float*)d_in[15] };
    const float* w_hh[4]  = { (const float*)d_in[4],  (const float*)d_in[8],
                              (const float*)d_in[12], (const float*)d_in[16] };
    const float* b_ih[4]  = { (const float*)d_in[5],  (const float*)d_in[9],
                              (const float*)d_in[13], (const float*)d_in[17] };
    const float* b_hh[4]  = { (const float*)d_in[6],  (const float*)d_in[10],
                              (const float*)d_in[14], (const float*)d_in[18] };
    const float* wl1      = (const float*)d_in[19];
    const float* wl2      = (const float*)d_in[20];
    const float* bl2      = (const float*)d_in[21];
    float* outb = (float*)d_out;

    float *xpA, *xpB, *f1, *r1, *wl1T, *pooled;
    float4* whhT4;
    __nv_bfloat16 *Ahi, *Alo, *Wb;
    cudaGetSymbolAddress((void**)&xpA,    g_xpA);
    cudaGetSymbolAddress((void**)&xpB,    g_xpB);
    cudaGetSymbolAddress((void**)&f1,     g_f1);
    cudaGetSymbolAddress((void**)&r1,     g_r1);
    cudaGetSymbolAddress((void**)&whhT4,  g_whhT4);
    cudaGetSymbolAddress((void**)&wl1T,   g_wl1T);
    cudaGetSymbolAddress((void**)&pooled, g_pooled);
    cudaGetSymbolAddress((void**)&Ahi,    g_Ahi);
    cudaGetSymbolAddress((void**)&Alo,    g_Alo);
    cudaGetSymbolAddress((void**)&Wb,     g_W);

    cudaFuncSetAttribute(proj_mma, cudaFuncAttributeMaxDynamicSharedMemorySize, SMEM_PROJ);

    // 0: fused prep; 1: weight conversions; 2: input conversion
    prep_kernel<<<(4 * HH * HH + 255) / 256, 256>>>(
        w_hh[0], w_hh[1], w_hh[2], w_hh[3], wl1, whhT4, wl1T, pooled);
    conv_w_all<<<(4 * GG * KP + 255) / 256, 256>>>(w_ih[0], w_ih[1], w_ih[2], w_ih[3], Wb);
    conv_bx_kernel<<<(int)(((size_t)MM * KP + 255) / 256), 256>>>(bx, Ahi, Alo);

    dim3 pg(GG / 128, MM / 128);  // (4, 1200)

    // layer-0 projections
    proj_mma<<<pg, 256, SMEM_PROJ>>>(Ahi, Alo, Wb, Wb + (size_t)GG * KP,
                                     b_ih[0], b_hh[0], xpA);
    proj_mma<<<pg, 256, SMEM_PROJ>>>(Ahi, Alo, Wb + (size_t)2 * GG * KP, Wb + (size_t)3 * GG * KP,
                                     b_ih[1], b_hh[1], xpB);
    // layer-0 recurrence -> writes bf16 hi/lo split directly into Ahi/Alo (mode 1)
    lstm_kernel<<<128, 512>>>(xpA, xpB, whhT4, whhT4 + HH * HH, hf,
                              nullptr, nullptr, 0, Ahi, Alo, 1);

    // layer-1 projections
    proj_mma<<<pg, 256, SMEM_PROJ>>>(Ahi, Alo, Wb + (size_t)4 * GG * KP, Wb + (size_t)5 * GG * KP,
                                     b_ih[2], b_hh[2], xpA);
    proj_mma<<<pg, 256, SMEM_PROJ>>>(Ahi, Alo, Wb + (size_t)6 * GG * KP, Wb + (size_t)7 * GG * KP,
                                     b_ih[3], b_hh[3], xpB);
    // layer-1 recurrence -> f1, r1 (mode 0)
    lstm_kernel<<<128, 512>>>(xpA, xpB, whhT4 + 2 * HH * HH, whhT4 + 3 * HH * HH, hf,
                              f1, r1, HH, nullptr, nullptr, 0);

    // classifier + maxpool
    dim3 cg(BB, (TN + CTT - 1) / CTT);
    cls_kernel<<<cg, 256>>>(f1, r1, bx, hf, wl1T, pooled);
    // head + b_y passthrough
    out_kernel<<<BB, 128>>>(pooled, wl2, bl2, by, outb, out_size);
}

// round 13
// speedup vs baseline: 1.3364x; 1.3364x over previous
#include <cuda_runtime.h>
#include <cuda_bf16.h>
#include <math.h>
#include <cstdint>

// Problem dims
#define BB 512
#define TN 300
#define DD 200
#define HH 128
#define GG 512   // 4*H
#define MM (TN*BB)      // 153600 rows
#define KP 256          // padded K per segment

// ---------------- static device scratch ----------------
__device__ float g_xpA[(size_t)TN * BB * GG];
__device__ float g_xpB[(size_t)TN * BB * GG];
__device__ float g_f1 [(size_t)TN * BB * HH];
__device__ float g_r1 [(size_t)TN * BB * HH];
__device__ float4 g_whhT4[4 * HH * HH];          // [mat][k][h] -> (g0,g1,g2,g3)
__device__ float g_wl1T[456 * HH];
__device__ float g_pooled[BB * HH];
__device__ __nv_bfloat16 g_Ahi[(size_t)MM * KP];
__device__ __nv_bfloat16 g_Alo[(size_t)MM * KP];
__device__ __nv_bfloat16 g_W[4 * 2 * GG * KP];   // [proj][hi/lo][512][256]

__device__ __forceinline__ void atomicMaxF(float* addr, float v) {
    if (v >= 0.f) atomicMax((int*)addr, __float_as_int(v));
    else          atomicMin((unsigned int*)addr, __float_as_uint(v));
}

// ================= PTX helpers =================
__device__ __forceinline__ uint32_t smem_u32(const void* p) {
    uint32_t addr;
    asm("{ .reg .u64 tmp; cvta.to.shared.u64 tmp, %1; cvt.u32.u64 %0, tmp; }"
        : "=r"(addr) : "l"(p));
    return addr;
}
#define CP_ASYNC16(dst, src) \
    asm volatile("cp.async.ca.shared.global [%0], [%1], 16;" :: "r"(dst), "l"(src))
#define CP_COMMIT() asm volatile("cp.async.commit_group;" ::: "memory")
#define CP_WAIT1()  asm volatile("cp.async.wait_group 1;" ::: "memory")
#define CP_WAIT0()  asm volatile("cp.async.wait_group 0;" ::: "memory")

__device__ __forceinline__ void ldsm_x4(uint32_t& r0, uint32_t& r1, uint32_t& r2, uint32_t& r3,
                                        uint32_t addr) {
    asm volatile("ldmatrix.sync.aligned.m8n8.x4.shared.b16 {%0,%1,%2,%3}, [%4];"
        : "=r"(r0), "=r"(r1), "=r"(r2), "=r"(r3) : "r"(addr));
}
__device__ __forceinline__ void mma16816(float* d, const uint32_t* a, uint32_t b0, uint32_t b1) {
    asm volatile(
        "mma.sync.aligned.m16n8k16.row.col.f32.bf16.bf16.f32 "
        "{%0,%1,%2,%3}, {%4,%5,%6,%7}, {%8,%9}, {%0,%1,%2,%3};"
        : "+f"(d[0]), "+f"(d[1]), "+f"(d[2]), "+f"(d[3])
        : "r"(a[0]), "r"(a[1]), "r"(a[2]), "r"(a[3]), "r"(b0), "r"(b1));
}

// Packed fp32 pair (FFMA2) helpers
typedef unsigned long long u64t;
__device__ __forceinline__ u64t pack2(float a, float b) {
    u64t r; asm("mov.b64 %0, {%1,%2};" : "=l"(r) : "f"(a), "f"(b)); return r;
}
__device__ __forceinline__ void unpack2(u64t v, float& a, float& b) {
    asm("mov.b64 {%0,%1}, %2;" : "=f"(a), "=f"(b) : "l"(v));
}
__device__ __forceinline__ u64t fma2(u64t a, u64t b, u64t c) {
    u64t d; asm("fma.rn.f32x2 %0, %1, %2, %3;" : "=l"(d) : "l"(a), "l"(b), "l"(c)); return d;
}

// Fast activations (errors ~1e-5, budget 1e-3)
__device__ __forceinline__ float tanha(float x) {
    float y; asm("tanh.approx.f32 %0, %1;" : "=f"(y) : "f"(x)); return y;
}
__device__ __forceinline__ float sigf(float x) {
    float e; asm("ex2.approx.f32 %0, %1;" : "=f"(e) : "f"(-1.4426950408889634f * x));
    float r; asm("rcp.approx.f32 %0, %1;" : "=f"(r) : "f"(1.f + e));
    return r;
}

// ---------------- fused prep: whhT4 (x4), wl1T, pooled init ----------------
__global__ void prep_kernel(const float* __restrict__ w0, const float* __restrict__ w1,
                            const float* __restrict__ w2, const float* __restrict__ w3,
                            const float* __restrict__ wl1,
                            float4* __restrict__ whhT4, float* __restrict__ wl1T,
                            float* __restrict__ pooled) {
    int idx = blockIdx.x * blockDim.x + threadIdx.x;
    if (idx < 4 * HH * HH) {
        int mat = idx >> 14, rem = idx & 16383;
        int k = rem >> 7, h = rem & 127;
        const float* w = (mat == 0) ? w0 : (mat == 1) ? w1 : (mat == 2) ? w2 : w3;
        whhT4[idx] = make_float4(w[(0   + h) * HH + k], w[(128 + h) * HH + k],
                                 w[(256 + h) * HH + k], w[(384 + h) * HH + k]);
    }
    if (idx < 456 * HH) {
        int f = idx >> 7, o = idx & 127;
        wl1T[idx] = wl1[o * 456 + f];
    }
    if (idx < BB * HH) pooled[idx] = -2.0f;
}

// ---------------- fp32 -> bf16 hi/lo conversions ----------------
__global__ void conv_bx_kernel(const float* __restrict__ bx,
                               __nv_bfloat16* __restrict__ hi, __nv_bfloat16* __restrict__ lo) {
    size_t idx = (size_t)blockIdx.x * blockDim.x + threadIdx.x;
    if (idx >= (size_t)MM * KP) return;
    int m = (int)(idx >> 8), k = (int)(idx & 255);
    int t = m >> 9, b = m & 511;
    float v = (k < DD) ? bx[(size_t)b * TN * DD + (size_t)t * DD + k] : 0.f;
    __nv_bfloat16 h = __float2bfloat16(v);
    hi[idx] = h;
    lo[idx] = __float2bfloat16(v - __bfloat162float(h));
}
// all 4 weights in one kernel: out layout [proj][hi/lo][512][256]
__global__ void conv_w_all(const float* __restrict__ w0, const float* __restrict__ w1,
                           const float* __restrict__ w2, const float* __restrict__ w3,
                           __nv_bfloat16* __restrict__ out) {
    int idx = blockIdx.x * blockDim.x + threadIdx.x;
    if (idx >= 4 * GG * KP) return;
    int p = idx / (GG * KP), rem = idx % (GG * KP);
    int n = rem >> 8, k = rem & 255;
    const float* w = (p == 0) ? w0 : (p == 1) ? w1 : (p == 2) ? w2 : w3;
    int K = (p < 2) ? DD : 2 * HH;
    float v = (k < K) ? w[(size_t)n * K + k] : 0.f;
    __nv_bfloat16 h = __float2bfloat16(v);
    out[(size_t)(2 * p) * GG * KP + rem] = h;
    out[(size_t)(2 * p + 1) * GG * KP + rem] = __float2bfloat16(v - __bfloat162float(h));
}

// ---------------- HMMA projection GEMM ----------------
#define SROW 144
#define TILE_B (128 * SROW)
#define SMEM_PROJ (4 * TILE_B)
__global__ __launch_bounds__(256) void proj_mma(
    const __nv_bfloat16* __restrict__ Ahi, const __nv_bfloat16* __restrict__ Alo,
    const __nv_bfloat16* __restrict__ Whi, const __nv_bfloat16* __restrict__ Wlo,
    const float* __restrict__ b1, const float* __restrict__ b2,
    float* __restrict__ C) {
    extern __shared__ __align__(16) unsigned char dsm[];
    __shared__ float bias[128];
    int tid = threadIdx.x, lane = tid & 31, wid = tid >> 5;
    int wm = wid & 3, wn = wid >> 2;
    int m0 = blockIdx.y * 128, n0 = blockIdx.x * 128;
    if (tid < 128) bias[tid] = b1[n0 + tid] + b2[n0 + tid];

    uint32_t sa0 = smem_u32(dsm);
    uint32_t sb0 = sa0 + 2 * TILE_B;
    const __nv_bfloat16* Asegs[3] = { Ahi, Ahi, Alo };
    const __nv_bfloat16* Wsegs[3] = { Whi, Wlo, Whi };
    const int total = 12;

    auto load_chunk = [&](int c, int buf) {
        int seg = c >> 2;
        int ko = (c & 3) * 64;
        const __nv_bfloat16* As = Asegs[seg] + (size_t)m0 * KP + ko;
        const __nv_bfloat16* Ws = Wsegs[seg] + (size_t)n0 * KP + ko;
#pragma unroll
        for (int i = 0; i < 4; i++) {
            int idx = tid + i * 256;
            int row = idx >> 3, w = idx & 7;
            CP_ASYNC16(sa0 + buf * TILE_B + row * SROW + w * 16,
                       As + (size_t)row * KP + w * 8);
            CP_ASYNC16(sb0 + buf * TILE_B + row * SROW + w * 16,
                       Ws + (size_t)row * KP + w * 8);
        }
        CP_COMMIT();
    };

    float acc[2][8][4] = {};
    load_chunk(0, 0);
    load_chunk(1, 1);

    for (int c = 0; c < total; c++) {
        int buf = c & 1;
        if (c + 1 < total) CP_WAIT1(); else CP_WAIT0();
        __syncthreads();
        uint32_t ab = sa0 + buf * TILE_B;
        uint32_t bb = sb0 + buf * TILE_B;
#pragma unroll
        for (int ks = 0; ks < 4; ks++) {
            uint32_t a[2][4], b[4][4];
#pragma unroll
            for (int mt = 0; mt < 2; mt++) {
                uint32_t addr = ab + (uint32_t)(wm * 32 + mt * 16 + (lane & 15)) * SROW
                                   + (uint32_t)(ks * 16 + ((lane & 16) ? 8 : 0)) * 2;
                ldsm_x4(a[mt][0], a[mt][1], a[mt][2], a[mt][3], addr);
            }
#pragma unroll
            for (int np = 0; np < 4; np++) {
                uint32_t addr = bb + (uint32_t)(wn * 64 + np * 16 + (lane & 7) + ((lane & 16) ? 8 : 0)) * SROW
                                   + (uint32_t)(ks * 16 + ((lane & 8) ? 8 : 0)) * 2;
                ldsm_x4(b[np][0], b[np][1], b[np][2], b[np][3], addr);
            }
#pragma unroll
            for (int mt = 0; mt < 2; mt++)
#pragma unroll
                for (int nt = 0; nt < 8; nt++)
                    mma16816(acc[mt][nt], a[mt], b[nt >> 1][(nt & 1) * 2],
                             b[nt >> 1][(nt & 1) * 2 + 1]);
        }
        __syncthreads();
        if (c + 2 < total) load_chunk(c + 2, buf);
    }

#pragma unroll
    for (int mt = 0; mt < 2; mt++)
#pragma unroll
        for (int nt = 0; nt < 8; nt++) {
            int row  = m0 + wm * 32 + mt * 16 + (lane >> 2);
            int colL = wn * 64 + nt * 8 + (lane & 3) * 2;
            int col  = n0 + colL;
            float2 v0 = { acc[mt][nt][0] + bias[colL], acc[mt][nt][1] + bias[colL + 1] };
            float2 v1 = { acc[mt][nt][2] + bias[colL], acc[mt][nt][3] + bias[colL + 1] };
            *(float2*)(C + (size_t)row * 512 + col) = v0;
            *(float2*)(C + (size_t)(row + 8) * 512 + col) = v1;
        }
}

// ---------------- fused bidirectional LSTM recurrence ----------------
// R4 structure (256 threads: hcol = tid&127, rh = tid>>7, 4 rows each, full k per thread)
// + smem-cached weights for k<64 (loaded once; t-invariant)
// + depth-8 register prefetch for the k>=64 global half (issued before the smem half)
// + h stored k-major packed {h,h} with pad-10 rows: 2x ld.shared.v2.u64 per k for 4 rows
// + approx activations; mode 1 writes bf16 hi/lo split directly (layer-0 -> layer-1 input).
#define HPAD 10
#define LSTM_WSM (64 * HH * sizeof(float4))                 // 131072
#define LSTM_SMEM (LSTM_WSM + 2 * HH * HPAD * sizeof(u64t)) // +20480 = 151552
__global__ __launch_bounds__(256) void lstm_kernel(
    const float* __restrict__ xpF, const float* __restrict__ xpB,
    const float4* __restrict__ whhT4F, const float4* __restrict__ whhT4B,
    const float* __restrict__ hf,
    float* __restrict__ outF, float* __restrict__ outB, int outStride,
    __nv_bfloat16* __restrict__ ohi, __nv_bfloat16* __restrict__ olo, int mode) {
    extern __shared__ __align__(16) unsigned char lsm[];
    float4* wsh = (float4*)lsm;                       // [64][HH]
    u64t* hshp  = (u64t*)(lsm + LSTM_WSM);            // [2][HH(k)][HPAD(row)] packed {h,h}
    int dir = blockIdx.x & 1;
    int rb = (blockIdx.x >> 1) * 8;
    const float*  xp  = dir ? xpB    : xpF;
    const float4* wT4 = dir ? whhT4B : whhT4F;
    float*        out = dir ? outB   : outF;
    int tid = threadIdx.x;
    int hcol = tid & 127;
    int rh = tid >> 7;          // 0..1
    int r0 = rh * 4;

    // one-time: cache k<64 weights in smem
    for (int i = tid; i < 64 * HH; i += 256) wsh[i] = wT4[i];

    float hfv = hf[hcol];
    float c[4];
#pragma unroll
    for (int r = 0; r < 4; r++) c[r] = hfv;
    if (rh == 0) {
        u64t hp = pack2(hfv, hfv);
#pragma unroll
        for (int r = 0; r < 8; r++) hshp[(size_t)hcol * HPAD + r] = hp;
    }
    __syncthreads();

    const float4* wpg = wT4 + (size_t)64 * HH + hcol;

    for (int t = 0; t < TN; t++) {
        int tef = dir ? (TN - 1 - t) : t;
        int cur = t & 1;
        const u64t* hcur = hshp + (size_t)cur * HH * HPAD;

        // xp loads early — latency hidden under the k-loop
        float xr[4][4];
        size_t rowbase = ((size_t)tef * BB + rb + r0) * GG + hcol;
#pragma unroll
        for (int r = 0; r < 4; r++) {
            const float* p = xp + rowbase + (size_t)r * GG;
            xr[r][0] = p[0];   xr[r][1] = p[128];
            xr[r][2] = p[256]; xr[r][3] = p[384];
        }

        // prefetch first global chunk (k=64..71) before the smem half
        float4 wc[8];
#pragma unroll
        for (int j = 0; j < 8; j++) wc[j] = wpg[(size_t)j * HH];

        u64t a01[4] = {0ull, 0ull, 0ull, 0ull};
        u64t a23[4] = {0ull, 0ull, 0ull, 0ull};

        // ---- smem half: k in [0,64) ----
#pragma unroll 8
        for (int k = 0; k < 64; k++) {
            float4 w4 = wsh[k * HH + hcol];
            const u64t* hp = hcur + k * HPAD + r0;
            ulonglong2 ha = *(const ulonglong2*)hp;
            ulonglong2 hb = *(const ulonglong2*)(hp + 2);
            u64t w01 = pack2(w4.x, w4.y);
            u64t w23 = pack2(w4.z, w4.w);
            a01[0] = fma2(ha.x, w01, a01[0]); a23[0] = fma2(ha.x, w23, a23[0]);
            a01[1] = fma2(ha.y, w01, a01[1]); a23[1] = fma2(ha.y, w23, a23[1]);
            a01[2] = fma2(hb.x, w01, a01[2]); a23[2] = fma2(hb.x, w23, a23[2]);
            a01[3] = fma2(hb.y, w01, a01[3]); a23[3] = fma2(hb.y, w23, a23[3]);
        }

        // ---- global half: k in [64,128), rolling depth-8 prefetch ----
#pragma unroll
        for (int kc = 0; kc < 64; kc += 8) {
            float4 wn[8];
            if (kc + 8 < 64) {
#pragma unroll
                for (int j = 0; j < 8; j++) wn[j] = wpg[(size_t)(kc + 8 + j) * HH];
            }
#pragma unroll
            for (int j = 0; j < 8; j++) {
                int k = 64 + kc + j;
                const u64t* hp = hcur + k * HPAD + r0;
                ulonglong2 ha = *(const ulonglong2*)hp;
                ulonglong2 hb = *(const ulonglong2*)(hp + 2);
                u64t w01 = pack2(wc[j].x, wc[j].y);
                u64t w23 = pack2(wc[j].z, wc[j].w);
                a01[0] = fma2(ha.x, w01, a01[0]); a23[0] = fma2(ha.x, w23, a23[0]);
                a01[1] = fma2(ha.y, w01, a01[1]); a23[1] = fma2(ha.y, w23, a23[1]);
                a01[2] = fma2(hb.x, w01, a01[2]); a23[2] = fma2(hb.x, w23, a23[2]);
                a01[3] = fma2(hb.y, w01, a01[3]); a23[3] = fma2(hb.y, w23, a23[3]);
            }
            if (kc + 8 < 64) {
#pragma unroll
                for (int j = 0; j < 8; j++) wc[j] = wn[j];
            }
        }

        // ---- epilogue: gates, state update, h write ----
        u64t* hw = hshp + ((size_t)(cur ^ 1) * HH + hcol) * HPAD + r0;
        u64t hnew[4];
#pragma unroll
        for (int r = 0; r < 4; r++) {
            float gi, gf_, gc, go;
            unpack2(a01[r], gi, gf_);
            unpack2(a23[r], gc, go);
            gi  += xr[r][0]; gf_ += xr[r][1];
            gc  += xr[r][2]; go  += xr[r][3];
            float ig = sigf(gi), fg = sigf(gf_);
            float cc = tanha(gc), og = sigf(go);
            float cv = fg * c[r] + ig * cc;
            c[r] = cv;
            float hv = og * tanha(cv);
            hnew[r] = pack2(hv, hv);
            size_t row = (size_t)tef * BB + rb + r0 + r;
            if (mode == 0) {
                out[row * outStride + hcol] = hv;
            } else {
                size_t o = row * KP + dir * 128 + hcol;
                __nv_bfloat16 hh = __float2bfloat16(hv);
                ohi[o] = hh;
                olo[o] = __float2bfloat16(hv - __bfloat162float(hh));
            }
        }
        ulonglong2 s0; s0.x = hnew[0]; s0.y = hnew[1];
        ulonglong2 s1; s1.x = hnew[2]; s1.y = hnew[3];
        *(ulonglong2*)hw = s0;
        *(ulonglong2*)(hw + 2) = s1;
        __syncthreads();
    }
}

// ---------------- classifier: h = tanh(data @ w_l1^T), max over t ----------------
#define CTT 16
__global__ __launch_bounds__(256) void cls_kernel(
    const float* __restrict__ f1, const float* __restrict__ r1,
    const float* __restrict__ bx, const float* __restrict__ hf,
    const float* __restrict__ wl1T, float* __restrict__ pooled) {
    __shared__ float ds[CTT][456];
    int b = blockIdx.x;
    int tile = blockIdx.y;
    int tid = threadIdx.x;
    for (int idx = tid; idx < CTT * 456; idx += 256) {
        int tt = idx / 456, f = idx % 456;
        int t = tile * CTT + tt;
        float v = 0.f;
        if (t < TN) {
            if (f < 128) {
                v = (t == 0) ? hf[f] : f1[((size_t)t * BB + b) * HH + f];
            } else if (f < 328) {
                v = bx[(size_t)b * TN * DD + (size_t)t * DD + (f - 128)];
            } else {
                int j = f - 328;
                v = (t == TN - 1) ? hf[j] : r1[((size_t)(TN - 2 - t) * BB + b) * HH + j];
            }
        }
        ds[tt][f] = v;
    }
    __syncthreads();

    int o2 = (tid & 63) * 2;
    int tsub = tid >> 6;
    float acc[4][2];
#pragma unroll
    for (int q = 0; q < 4; q++) { acc[q][0] = 0.f; acc[q][1] = 0.f; }
    for (int f = 0; f < 456; f++) {
        float2 w = *(const float2*)(wl1T + f * HH + o2);
#pragma unroll
        for (int q = 0; q < 4; q++) {
            float dv = ds[tsub + q * 4][f];
            acc[q][0] += dv * w.x;
            acc[q][1] += dv * w.y;
        }
    }
    float m0v = -2.f, m1v = -2.f;
#pragma unroll
    for (int q = 0; q < 4; q++) {
        int t = tile * CTT + tsub + q * 4;
        if (t < TN) {
            m0v = fmaxf(m0v, tanha(acc[q][0]));
            m1v = fmaxf(m1v, tanha(acc[q][1]));
        }
    }
    atomicMaxF(&pooled[b * HH + o2],     m0v);
    atomicMaxF(&pooled[b * HH + o2 + 1], m1v);
}

// ---------------- final head ----------------
__global__ void out_kernel(const float* __restrict__ pooled,
                           const float* __restrict__ wl2, const float* __restrict__ bl2,
                           const int* __restrict__ by, float* __restrict__ outb,
                           int out_size) {
    __shared__ float sh[128];
    int b = blockIdx.x, tid = threadIdx.x;
    float p = pooled[b * 128 + tid];
    for (int o = 0; o < 4; o++) {
        float v = p * wl2[o * 128 + tid];
        sh[tid] = v;
        __syncthreads();
        if (tid < 64) sh[tid] += sh[tid + 64];
        __syncthreads();
        if (tid < 32) {
            float s = sh[tid] + sh[tid + 32];
            for (int off = 16; off; off >>= 1) s += __shfl_down_sync(0xffffffffu, s, off);
            if (tid == 0) outb[b * 4 + o] = s + bl2[o];
        }
        __syncthreads();
    }
    if (tid == 0 && out_size >= BB * 4 + BB) outb[BB * 4 + b] = (float)by[b];
}

// ---------------- launch ----------------
extern "C" void kernel_launch(void* const* d_in, const int* in_sizes, int n_in,
                              void* d_out, int out_size) {
    const float* bx       = (const float*)d_in[0];
    const int*   by       = (const int*)  d_in[1];
    const float* hf       = (const float*)d_in[2];
    const float* w_ih[4]  = { (const float*)d_in[3],  (const float*)d_in[7],
                              (const float*)d_in[11], (const float*)d_in[15] };
    const float* w_hh[4]  = { (const float*)d_in[4],  (const float*)d_in[8],
                              (const float*)d_in[12], (const float*)d_in[16] };
    const float* b_ih[4]  = { (const float*)d_in[5],  (const float*)d_in[9],
                              (const float*)d_in[13], (const float*)d_in[17] };
    const float* b_hh[4]  = { (const float*)d_in[6],  (const float*)d_in[10],
                              (const float*)d_in[14], (const float*)d_in[18] };
    const float* wl1      = (const float*)d_in[19];
    const float* wl2      = (const float*)d_in[20];
    const float* bl2      = (const float*)d_in[21];
    float* outb = (float*)d_out;

    float *xpA, *xpB, *f1, *r1, *wl1T, *pooled;
    float4* whhT4;
    __nv_bfloat16 *Ahi, *Alo, *Wb;
    cudaGetSymbolAddress((void**)&xpA,    g_xpA);
    cudaGetSymbolAddress((void**)&xpB,    g_xpB);
    cudaGetSymbolAddress((void**)&f1,     g_f1);
    cudaGetSymbolAddress((void**)&r1,     g_r1);
    cudaGetSymbolAddress((void**)&whhT4,  g_whhT4);
    cudaGetSymbolAddress((void**)&wl1T,   g_wl1T);
    cudaGetSymbolAddress((void**)&pooled, g_pooled);
    cudaGetSymbolAddress((void**)&Ahi,    g_Ahi);
    cudaGetSymbolAddress((void**)&Alo,    g_Alo);
    cudaGetSymbolAddress((void**)&Wb,     g_W);

    cudaFuncSetAttribute(proj_mma, cudaFuncAttributeMaxDynamicSharedMemorySize, SMEM_PROJ);
    cudaFuncSetAttribute(lstm_kernel, cudaFuncAttributeMaxDynamicSharedMemorySize, LSTM_SMEM);

    // 0: fused prep; 1: weight conversions; 2: input conversion
    prep_kernel<<<(4 * HH * HH + 255) / 256, 256>>>(
        w_hh[0], w_hh[1], w_hh[2], w_hh[3], wl1, whhT4, wl1T, pooled);
    conv_w_all<<<(4 * GG * KP + 255) / 256, 256>>>(w_ih[0], w_ih[1], w_ih[2], w_ih[3], Wb);
    conv_bx_kernel<<<(int)(((size_t)MM * KP + 255) / 256), 256>>>(bx, Ahi, Alo);

    dim3 pg(GG / 128, MM / 128);  // (4, 1200)

    // layer-0 projections
    proj_mma<<<pg, 256, SMEM_PROJ>>>(Ahi, Alo, Wb, Wb + (size_t)GG * KP,
                                     b_ih[0], b_hh[0], xpA);
    proj_mma<<<pg, 256, SMEM_PROJ>>>(Ahi, Alo, Wb + (size_t)2 * GG * KP, Wb + (size_t)3 * GG * KP,
                                     b_ih[1], b_hh[1], xpB);
    // layer-0 recurrence -> writes bf16 hi/lo split directly into Ahi/Alo (mode 1)
    lstm_kernel<<<128, 256, LSTM_SMEM>>>(xpA, xpB, whhT4, whhT4 + HH * HH, hf,
                                         nullptr, nullptr, 0, Ahi, Alo, 1);

    // layer-1 projections
    proj_mma<<<pg, 256, SMEM_PROJ>>>(Ahi, Alo, Wb + (size_t)4 * GG * KP, Wb + (size_t)5 * GG * KP,
                                     b_ih[2], b_hh[2], xpA);
    proj_mma<<<pg, 256, SMEM_PROJ>>>(Ahi, Alo, Wb + (size_t)6 * GG * KP, Wb + (size_t)7 * GG * KP,
                                     b_ih[3], b_hh[3], xpB);
    // layer-1 recurrence -> f1, r1 (mode 0)
    lstm_kernel<<<128, 256, LSTM_SMEM>>>(xpA, xpB, whhT4 + 2 * HH * HH, whhT4 + 3 * HH * HH, hf,
                                         f1, r1, HH, nullptr, nullptr, 0);

    // classifier + maxpool
    dim3 cg(BB, (TN + CTT - 1) / CTT);
    cls_kernel<<<cg, 256>>>(f1, r1, bx, hf, wl1T, pooled);
    // head + b_y passthrough
    out_kernel<<<BB, 128>>>(pooled, wl2, bl2, by, outb, out_size);
}

// round 15
// speedup vs baseline: 2.1313x; 1.5949x over previous
#include <cuda_runtime.h>
#include <cuda_bf16.h>
#include <math.h>
#include <cstdint>

// Problem dims
#define BB 512
#define TN 300
#define DD 200
#define HH 128
#define GG 512   // 4*H
#define MM (TN*BB)      // 153600 rows
#define KP 256          // padded K per segment

// ---------------- static device scratch ----------------
__device__ float g_xpA[(size_t)TN * BB * GG];
__device__ float g_xpB[(size_t)TN * BB * GG];
__device__ float g_f1 [(size_t)TN * BB * HH];
__device__ float g_r1 [(size_t)TN * BB * HH];
__device__ float4 g_whhT4[4 * HH * HH];          // [mat][k][h] -> (g0,g1,g2,g3)
__device__ float g_wl1T[456 * HH];
__device__ float g_pooled[BB * HH];
__device__ __nv_bfloat16 g_Ahi[(size_t)MM * KP];
__device__ __nv_bfloat16 g_Alo[(size_t)MM * KP];
__device__ __nv_bfloat16 g_W[4 * 2 * GG * KP];   // [proj][hi/lo][512][256]

__device__ __forceinline__ void atomicMaxF(float* addr, float v) {
    if (v >= 0.f) atomicMax((int*)addr, __float_as_int(v));
    else          atomicMin((unsigned int*)addr, __float_as_uint(v));
}

// ================= PTX helpers =================
__device__ __forceinline__ uint32_t smem_u32(const void* p) {
    uint32_t addr;
    asm("{ .reg .u64 tmp; cvta.to.shared.u64 tmp, %1; cvt.u32.u64 %0, tmp; }"
        : "=r"(addr) : "l"(p));
    return addr;
}
#define CP_ASYNC16(dst, src) \
    asm volatile("cp.async.ca.shared.global [%0], [%1], 16;" :: "r"(dst), "l"(src))
#define CP_COMMIT() asm volatile("cp.async.commit_group;" ::: "memory")
#define CP_WAIT1()  asm volatile("cp.async.wait_group 1;" ::: "memory")
#define CP_WAIT0()  asm volatile("cp.async.wait_group 0;" ::: "memory")

__device__ __forceinline__ void ldsm_x4(uint32_t& r0, uint32_t& r1, uint32_t& r2, uint32_t& r3,
                                        uint32_t addr) {
    asm volatile("ldmatrix.sync.aligned.m8n8.x4.shared.b16 {%0,%1,%2,%3}, [%4];"
        : "=r"(r0), "=r"(r1), "=r"(r2), "=r"(r3) : "r"(addr));
}
__device__ __forceinline__ void mma16816(float* d, const uint32_t* a, uint32_t b0, uint32_t b1) {
    asm volatile(
        "mma.sync.aligned.m16n8k16.row.col.f32.bf16.bf16.f32 "
        "{%0,%1,%2,%3}, {%4,%5,%6,%7}, {%8,%9}, {%0,%1,%2,%3};"
        : "+f"(d[0]), "+f"(d[1]), "+f"(d[2]), "+f"(d[3])
        : "r"(a[0]), "r"(a[1]), "r"(a[2]), "r"(a[3]), "r"(b0), "r"(b1));
}

// Packed fp32 pair (FFMA2) helpers
typedef unsigned long long u64t;
__device__ __forceinline__ u64t pack2(float a, float b) {
    u64t r; asm("mov.b64 %0, {%1,%2};" : "=l"(r) : "f"(a), "f"(b)); return r;
}
__device__ __forceinline__ void unpack2(u64t v, float& a, float& b) {
    asm("mov.b64 {%0,%1}, %2;" : "=f"(a), "=f"(b) : "l"(v));
}
__device__ __forceinline__ u64t fma2(u64t a, u64t b, u64t c) {
    u64t d; asm("fma.rn.f32x2 %0, %1, %2, %3;" : "=l"(d) : "l"(a), "l"(b), "l"(c)); return d;
}

// Fast activations (errors ~1e-5, budget 1e-3)
__device__ __forceinline__ float tanha(float x) {
    float y; asm("tanh.approx.f32 %0, %1;" : "=f"(y) : "f"(x)); return y;
}
// sigmoid(x) = 0.5 + 0.5*tanh(x/2): 1 MUFU instead of ex2+rcp (2 MUFU)
__device__ __forceinline__ float sigf(float x) {
    return fmaf(tanha(0.5f * x), 0.5f, 0.5f);
}

// ---------------- fused prep: whhT4, wl1T, pooled, conv_w, conv_bx (ONE launch) ----------------
__global__ void fused_prep(const float* __restrict__ wh0, const float* __restrict__ wh1,
                           const float* __restrict__ wh2, const float* __restrict__ wh3,
                           const float* __restrict__ wl1,
                           const float* __restrict__ wi0, const float* __restrict__ wi1,
                           const float* __restrict__ wi2, const float* __restrict__ wi3,
                           const float* __restrict__ bx,
                           float4* __restrict__ whhT4, float* __restrict__ wl1T,
                           float* __restrict__ pooled,
                           __nv_bfloat16* __restrict__ Wb,
                           __nv_bfloat16* __restrict__ Ahi, __nv_bfloat16* __restrict__ Alo) {
    size_t idx = (size_t)blockIdx.x * blockDim.x + threadIdx.x;
    if (idx < 4 * HH * HH) {
        int mat = (int)(idx >> 14), rem = (int)(idx & 16383);
        int k = rem >> 7, h = rem & 127;
        const float* w = (mat == 0) ? wh0 : (mat == 1) ? wh1 : (mat == 2) ? wh2 : wh3;
        whhT4[idx] = make_float4(w[(0   + h) * HH + k], w[(128 + h) * HH + k],
                                 w[(256 + h) * HH + k], w[(384 + h) * HH + k]);
    }
    if (idx < 456 * HH) {
        int f = (int)(idx >> 7), o = (int)(idx & 127);
        wl1T[idx] = wl1[o * 456 + f];
    }
    if (idx < BB * HH) pooled[idx] = -2.0f;
    if (idx < (size_t)4 * GG * KP) {
        int p = (int)(idx / (GG * KP)), rem = (int)(idx % (GG * KP));
        int n = rem >> 8, k = rem & 255;
        const float* w = (p == 0) ? wi0 : (p == 1) ? wi1 : (p == 2) ? wi2 : wi3;
        int K = (p < 2) ? DD : 2 * HH;
        float v = (k < K) ? w[(size_t)n * K + k] : 0.f;
        __nv_bfloat16 h = __float2bfloat16(v);
        Wb[(size_t)(2 * p) * GG * KP + rem] = h;
        Wb[(size_t)(2 * p + 1) * GG * KP + rem] = __float2bfloat16(v - __bfloat162float(h));
    }
    if (idx < (size_t)MM * KP) {
        int m = (int)(idx >> 8), k = (int)(idx & 255);
        int t = m >> 9, b = m & 511;
        float v = (k < DD) ? bx[(size_t)b * TN * DD + (size_t)t * DD + k] : 0.f;
        __nv_bfloat16 h = __float2bfloat16(v);
        Ahi[idx] = h;
        Alo[idx] = __float2bfloat16(v - __bfloat162float(h));
    }
}

// no-op spacer so the fixed ncu sample slot lands on lstm_kernel
__global__ void dummy_kernel() {}

// ---------------- HMMA projection GEMM ----------------
#define SROW 144
#define TILE_B (128 * SROW)
#define SMEM_PROJ (4 * TILE_B)
__global__ __launch_bounds__(256) void proj_mma(
    const __nv_bfloat16* __restrict__ Ahi, const __nv_bfloat16* __restrict__ Alo,
    const __nv_bfloat16* __restrict__ Whi, const __nv_bfloat16* __restrict__ Wlo,
    const float* __restrict__ b1, const float* __restrict__ b2,
    float* __restrict__ C) {
    extern __shared__ __align__(16) unsigned char dsm[];
    __shared__ float bias[128];
    int tid = threadIdx.x, lane = tid & 31, wid = tid >> 5;
    int wm = wid & 3, wn = wid >> 2;
    int m0 = blockIdx.y * 128, n0 = blockIdx.x * 128;
    if (tid < 128) bias[tid] = b1[n0 + tid] + b2[n0 + tid];

    uint32_t sa0 = smem_u32(dsm);
    uint32_t sb0 = sa0 + 2 * TILE_B;
    const __nv_bfloat16* Asegs[3] = { Ahi, Ahi, Alo };
    const __nv_bfloat16* Wsegs[3] = { Whi, Wlo, Whi };
    const int total = 12;

    auto load_chunk = [&](int c, int buf) {
        int seg = c >> 2;
        int ko = (c & 3) * 64;
        const __nv_bfloat16* As = Asegs[seg] + (size_t)m0 * KP + ko;
        const __nv_bfloat16* Ws = Wsegs[seg] + (size_t)n0 * KP + ko;
#pragma unroll
        for (int i = 0; i < 4; i++) {
            int idx = tid + i * 256;
            int row = idx >> 3, w = idx & 7;
            CP_ASYNC16(sa0 + buf * TILE_B + row * SROW + w * 16,
                       As + (size_t)row * KP + w * 8);
            CP_ASYNC16(sb0 + buf * TILE_B + row * SROW + w * 16,
                       Ws + (size_t)row * KP + w * 8);
        }
        CP_COMMIT();
    };

    float acc[2][8][4] = {};
    load_chunk(0, 0);
    load_chunk(1, 1);

    for (int c = 0; c < total; c++) {
        int buf = c & 1;
        if (c + 1 < total) CP_WAIT1(); else CP_WAIT0();
        __syncthreads();
        uint32_t ab = sa0 + buf * TILE_B;
        uint32_t bb = sb0 + buf * TILE_B;
#pragma unroll
        for (int ks = 0; ks < 4; ks++) {
            uint32_t a[2][4], b[4][4];
#pragma unroll
            for (int mt = 0; mt < 2; mt++) {
                uint32_t addr = ab + (uint32_t)(wm * 32 + mt * 16 + (lane & 15)) * SROW
                                   + (uint32_t)(ks * 16 + ((lane & 16) ? 8 : 0)) * 2;
                ldsm_x4(a[mt][0], a[mt][1], a[mt][2], a[mt][3], addr);
            }
#pragma unroll
            for (int np = 0; np < 4; np++) {
                uint32_t addr = bb + (uint32_t)(wn * 64 + np * 16 + (lane & 7) + ((lane & 16) ? 8 : 0)) * SROW
                                   + (uint32_t)(ks * 16 + ((lane & 8) ? 8 : 0)) * 2;
                ldsm_x4(b[np][0], b[np][1], b[np][2], b[np][3], addr);
            }
#pragma unroll
            for (int mt = 0; mt < 2; mt++)
#pragma unroll
                for (int nt = 0; nt < 8; nt++)
                    mma16816(acc[mt][nt], a[mt], b[nt >> 1][(nt & 1) * 2],
                             b[nt >> 1][(nt & 1) * 2 + 1]);
        }
        __syncthreads();
        if (c + 2 < total) load_chunk(c + 2, buf);
    }

#pragma unroll
    for (int mt = 0; mt < 2; mt++)
#pragma unroll
        for (int nt = 0; nt < 8; nt++) {
            int row  = m0 + wm * 32 + mt * 16 + (lane >> 2);
            int colL = wn * 64 + nt * 8 + (lane & 3) * 2;
            int col  = n0 + colL;
            float2 v0 = { acc[mt][nt][0] + bias[colL], acc[mt][nt][1] + bias[colL + 1] };
            float2 v1 = { acc[mt][nt][2] + bias[colL], acc[mt][nt][3] + bias[colL + 1] };
            *(float2*)(C + (size_t)row * 512 + col) = v0;
            *(float2*)(C + (size_t)(row + 8) * 512 + col) = v1;
        }
}

// ---------------- fused bidirectional LSTM recurrence ----------------
// 256 threads: hcol = tid&127, rh = tid>>7, 4 rows each, full k per thread.
// Weights for k<KS cached in smem PRE-PACKED as u64 gate-pairs:
//   wsh2[k*256 + hcol] = {g0,g1},  wsh2[k*256 + 128 + hcol] = {g2,g3}
// k>=KS tail streamed from global with rolling depth-8 prefetch.
// h stored k-major packed {h,h} with pad-10 rows. Approx activations.
// mode 1 writes bf16 hi/lo split directly (layer-0 -> layer-1 input).
#define HPAD 10
#define KS 96
#define LSTM_WSM (KS * 2 * HH * sizeof(u64t))               // 196608
#define LSTM_SMEM (LSTM_WSM + 2 * HH * HPAD * sizeof(u64t)) // +20480 = 217088
__global__ __launch_bounds__(256) void lstm_kernel(
    const float* __restrict__ xpF, const float* __restrict__ xpB,
    const float4* __restrict__ whhT4F, const float4* __restrict__ whhT4B,
    const float* __restrict__ hf,
    float* __restrict__ outF, float* __restrict__ outB, int outStride,
    __nv_bfloat16* __restrict__ ohi, __nv_bfloat16* __restrict__ olo, int mode) {
    extern __shared__ __align__(16) unsigned char lsm[];
    u64t* wsh2 = (u64t*)lsm;                          // [KS][2][HH] packed gate pairs
    u64t* hshp = (u64t*)(lsm + LSTM_WSM);             // [2][HH(k)][HPAD(row)] packed {h,h}
    int dir = blockIdx.x & 1;
    int rb = (blockIdx.x >> 1) * 8;
    const float*  xp  = dir ? xpB    : xpF;
    const float4* wT4 = dir ? whhT4B : whhT4F;
    float*        out = dir ? outB   : outF;
    int tid = threadIdx.x;
    int hcol = tid & 127;
    int rh = tid >> 7;          // 0..1
    int r0 = rh * 4;

    // one-time: cache k<KS weights in smem, pre-packed as u64 pairs
    for (int i = tid; i < KS * HH; i += 256) {
        int k = i >> 7, h = i & 127;
        float4 w4 = wT4[i];
        wsh2[k * 256 + h]       = pack2(w4.x, w4.y);
        wsh2[k * 256 + 128 + h] = pack2(w4.z, w4.w);
    }

    float hfv = hf[hcol];
    float c[4];
#pragma unroll
    for (int r = 0; r < 4; r++) c[r] = hfv;
    if (rh == 0) {
        u64t hp = pack2(hfv, hfv);
#pragma unroll
        for (int r = 0; r < 8; r++) hshp[(size_t)hcol * HPAD + r] = hp;
    }
    __syncthreads();

    const float4* wpg = wT4 + (size_t)KS * HH + hcol;

    for (int t = 0; t < TN; t++) {
        int tef = dir ? (TN - 1 - t) : t;
        int cur = t & 1;
        const u64t* hcur = hshp + (size_t)cur * HH * HPAD;

        // xp loads early — latency hidden under the k-loop
        float xr[4][4];
        size_t rowbase = ((size_t)tef * BB + rb + r0) * GG + hcol;
#pragma unroll
        for (int r = 0; r < 4; r++) {
            const float* p = xp + rowbase + (size_t)r * GG;
            xr[r][0] = p[0];   xr[r][1] = p[128];
            xr[r][2] = p[256]; xr[r][3] = p[384];
        }

        // prefetch first global tail chunk (k=KS..KS+7) before the smem bulk
        float4 wc[8];
#pragma unroll
        for (int j = 0; j < 8; j++) wc[j] = wpg[(size_t)j * HH];

        u64t a01[4] = {0ull, 0ull, 0ull, 0ull};
        u64t a23[4] = {0ull, 0ull, 0ull, 0ull};

        // ---- smem bulk: k in [0,KS) ----
#pragma unroll 8
        for (int k = 0; k < KS; k++) {
            u64t w01 = wsh2[k * 256 + hcol];
            u64t w23 = wsh2[k * 256 + 128 + hcol];
            const u64t* hp = hcur + k * HPAD + r0;
            ulonglong2 ha = *(const ulonglong2*)hp;
            ulonglong2 hb = *(const ulonglong2*)(hp + 2);
            a01[0] = fma2(ha.x, w01, a01[0]); a23[0] = fma2(ha.x, w23, a23[0]);
            a01[1] = fma2(ha.y, w01, a01[1]); a23[1] = fma2(ha.y, w23, a23[1]);
            a01[2] = fma2(hb.x, w01, a01[2]); a23[2] = fma2(hb.x, w23, a23[2]);
            a01[3] = fma2(hb.y, w01, a01[3]); a23[3] = fma2(hb.y, w23, a23[3]);
        }

        // ---- global tail: k in [KS,128), rolling depth-8 prefetch ----
#pragma unroll
        for (int kc = 0; kc < 128 - KS; kc += 8) {
            float4 wn[8];
            if (kc + 8 < 128 - KS) {
#pragma unroll
                for (int j = 0; j < 8; j++) wn[j] = wpg[(size_t)(kc + 8 + j) * HH];
            }
#pragma unroll
            for (int j = 0; j < 8; j++) {
                int k = KS + kc + j;
                const u64t* hp = hcur + k * HPAD + r0;
                ulonglong2 ha = *(const ulonglong2*)hp;
                ulonglong2 hb = *(const ulonglong2*)(hp + 2);
                u64t w01 = pack2(wc[j].x, wc[j].y);
                u64t w23 = pack2(wc[j].z, wc[j].w);
                a01[0] = fma2(ha.x, w01, a01[0]); a23[0] = fma2(ha.x, w23, a23[0]);
                a01[1] = fma2(ha.y, w01, a01[1]); a23[1] = fma2(ha.y, w23, a23[1]);
                a01[2] = fma2(hb.x, w01, a01[2]); a23[2] = fma2(hb.x, w23, a23[2]);
                a01[3] = fma2(hb.y, w01, a01[3]); a23[3] = fma2(hb.y, w23, a23[3]);
            }
            if (kc + 8 < 128 - KS) {
#pragma unroll
                for (int j = 0; j < 8; j++) wc[j] = wn[j];
            }
        }

        // ---- epilogue: gates, state update, h write ----
        u64t* hw = hshp + ((size_t)(cur ^ 1) * HH + hcol) * HPAD + r0;
        u64t hnew[4];
#pragma unroll
        for (int r = 0; r < 4; r++) {
            float gi, gf_, gc, go;
            unpack2(a01[r], gi, gf_);
            unpack2(a23[r], gc, go);
            gi  += xr[r][0]; gf_ += xr[r][1];
            gc  += xr[r][2]; go  += xr[r][3];
            float ig = sigf(gi), fg = sigf(gf_);
            float cc = tanha(gc), og = sigf(go);
            float cv = fg * c[r] + ig * cc;
            c[r] = cv;
            float hv = og * tanha(cv);
            hnew[r] = pack2(hv, hv);
            size_t row = (size_t)tef * BB + rb + r0 + r;
            if (mode == 0) {
                out[row * outStride + hcol] = hv;
            } else {
                size_t o = row * KP + dir * 128 + hcol;
                __nv_bfloat16 hh = __float2bfloat16(hv);
                ohi[o] = hh;
                olo[o] = __float2bfloat16(hv - __bfloat162float(hh));
            }
        }
        ulonglong2 s0; s0.x = hnew[0]; s0.y = hnew[1];
        ulonglong2 s1; s1.x = hnew[2]; s1.y = hnew[3];
        *(ulonglong2*)hw = s0;
        *(ulonglong2*)(hw + 2) = s1;
        __syncthreads();
    }
}

// ---------------- classifier: h = tanh(data @ w_l1^T), max over t ----------------
#define CTT 16
__global__ __launch_bounds__(256) void cls_kernel(
    const float* __restrict__ f1, const float* __restrict__ r1,
    const float* __restrict__ bx, const float* __restrict__ hf,
    const float* __restrict__ wl1T, float* __restrict__ pooled) {
    __shared__ float ds[CTT][456];
    int b = blockIdx.x;
    int tile = blockIdx.y;
    int tid = threadIdx.x;
    for (int idx = tid; idx < CTT * 456; idx += 256) {
        int tt = idx / 456, f = idx % 456;
        int t = tile * CTT + tt;
        float v = 0.f;
        if (t < TN) {
            if (f < 128) {
                v = (t == 0) ? hf[f] : f1[((size_t)t * BB + b) * HH + f];
            } else if (f < 328) {
                v = bx[(size_t)b * TN * DD + (size_t)t * DD + (f - 128)];
            } else {
                int j = f - 328;
                v = (t == TN - 1) ? hf[j] : r1[((size_t)(TN - 2 - t) * BB + b) * HH + j];
            }
        }
        ds[tt][f] = v;
    }
    __syncthreads();

    int o2 = (tid & 63) * 2;
    int tsub = tid >> 6;
    float acc[4][2];
#pragma unroll
    for (int q = 0; q < 4; q++) { acc[q][0] = 0.f; acc[q][1] = 0.f; }
    for (int f = 0; f < 456; f++) {
        float2 w = *(const float2*)(wl1T + f * HH + o2);
#pragma unroll
        for (int q = 0; q < 4; q++) {
            float dv = ds[tsub + q * 4][f];
            acc[q][0] += dv * w.x;
            acc[q][1] += dv * w.y;
        }
    }
    float m0v = -2.f, m1v = -2.f;
#pragma unroll
    for (int q = 0; q < 4; q++) {
        int t = tile * CTT + tsub + q * 4;
        if (t < TN) {
            m0v = fmaxf(m0v, tanha(acc[q][0]));
            m1v = fmaxf(m1v, tanha(acc[q][1]));
        }
    }
    atomicMaxF(&pooled[b * HH + o2],     m0v);
    atomicMaxF(&pooled[b * HH + o2 + 1], m1v);
}

// ---------------- final head ----------------
__global__ void out_kernel(const float* __restrict__ pooled,
                           const float* __restrict__ wl2, const float* __restrict__ bl2,
                           const int* __restrict__ by, float* __restrict__ outb,
                           int out_size) {
    __shared__ float sh[128];
    int b = blockIdx.x, tid = threadIdx.x;
    float p = pooled[b * 128 + tid];
    for (int o = 0; o < 4; o++) {
        float v = p * wl2[o * 128 + tid];
        sh[tid] = v;
        __syncthreads();
        if (tid < 64) sh[tid] += sh[tid + 64];
        __syncthreads();
        if (tid < 32) {
            float s = sh[tid] + sh[tid + 32];
            for (int off = 16; off; off >>= 1) s += __shfl_down_sync(0xffffffffu, s, off);
            if (tid == 0) outb[b * 4 + o] = s + bl2[o];
        }
        __syncthreads();
    }
    if (tid == 0 && out_size >= BB * 4 + BB) outb[BB * 4 + b] = (float)by[b];
}

// ---------------- launch ----------------
extern "C" void kernel_launch(void* const* d_in, const int* in_sizes, int n_in,
                              void* d_out, int out_size) {
    const float* bx       = (const float*)d_in[0];
    const int*   by       = (const int*)  d_in[1];
    const float* hf       = (const float*)d_in[2];
    const float* w_ih[4]  = { (const float*)d_in[3],  (const float*)d_in[7],
                              (const float*)d_in[11], (const float*)d_in[15] };
    const float* w_hh[4]  = { (const float*)d_in[4],  (const float*)d_in[8],
                              (const float*)d_in[12], (const float*)d_in[16] };
    const float* b_ih[4]  = { (const float*)d_in[5],  (const float*)d_in[9],
                              (const float*)d_in[13], (const float*)d_in[17] };
    const float* b_hh[4]  = { (const float*)d_in[6],  (const float*)d_in[10],
                              (const float*)d_in[14], (const float*)d_in[18] };
    const float* wl1      = (const float*)d_in[19];
    const float* wl2      = (const float*)d_in[20];
    const float* bl2      = (const float*)d_in[21];
    float* outb = (float*)d_out;

    float *xpA, *xpB, *f1, *r1, *wl1T, *pooled;
    float4* whhT4;
    __nv_bfloat16 *Ahi, *Alo, *Wb;
    cudaGetSymbolAddress((void**)&xpA,    g_xpA);
    cudaGetSymbolAddress((void**)&xpB,    g_xpB);
    cudaGetSymbolAddress((void**)&f1,     g_f1);
    cudaGetSymbolAddress((void**)&r1,     g_r1);
    cudaGetSymbolAddress((void**)&whhT4,  g_whhT4);
    cudaGetSymbolAddress((void**)&wl1T,   g_wl1T);
    cudaGetSymbolAddress((void**)&pooled, g_pooled);
    cudaGetSymbolAddress((void**)&Ahi,    g_Ahi);
    cudaGetSymbolAddress((void**)&Alo,    g_Alo);
    cudaGetSymbolAddress((void**)&Wb,     g_W);

    cudaFuncSetAttribute(proj_mma, cudaFuncAttributeMaxDynamicSharedMemorySize, SMEM_PROJ);
    cudaFuncSetAttribute(lstm_kernel, cudaFuncAttributeMaxDynamicSharedMemorySize, LSTM_SMEM);

    dim3 pg(GG / 128, MM / 128);  // (4, 1200)

    // 0: all prep/conversions in ONE launch
    fused_prep<<<(int)(((size_t)MM * KP + 255) / 256), 256>>>(
        w_hh[0], w_hh[1], w_hh[2], w_hh[3], wl1,
        w_ih[0], w_ih[1], w_ih[2], w_ih[3], bx,
        whhT4, wl1T, pooled, Wb, Ahi, Alo);

    // 1,2: layer-0 projections
    proj_mma<<<pg, 256, SMEM_PROJ>>>(Ahi, Alo, Wb, Wb + (size_t)GG * KP,
                                     b_ih[0], b_hh[0], xpA);
    proj_mma<<<pg, 256, SMEM_PROJ>>>(Ahi, Alo, Wb + (size_t)2 * GG * KP, Wb + (size_t)3 * GG * KP,
                                     b_ih[1], b_hh[1], xpB);
    // 3: spacer so the fixed ncu sample slot (launch idx 4 + harness poison) hits lstm
    dummy_kernel<<<1, 32>>>();
    // 4: layer-0 recurrence -> writes bf16 hi/lo split directly into Ahi/Alo (mode 1)
    lstm_kernel<<<128, 256, LSTM_SMEM>>>(xpA, xpB, whhT4, whhT4 + HH * HH, hf,
                                         nullptr, nullptr, 0, Ahi, Alo, 1);

    // 5,6: layer-1 projections
    proj_mma<<<pg, 256, SMEM_PROJ>>>(Ahi, Alo, Wb + (size_t)4 * GG * KP, Wb + (size_t)5 * GG * KP,
                                     b_ih[2], b_hh[2], xpA);
    proj_mma<<<pg, 256, SMEM_PROJ>>>(Ahi, Alo, Wb + (size_t)6 * GG * KP, Wb + (size_t)7 * GG * KP,
                                     b_ih[3], b_hh[3], xpB);
    // 7: layer-1 recurrence -> f1, r1 (mode 0)
    lstm_kernel<<<128, 256, LSTM_SMEM>>>(xpA, xpB, whhT4 + 2 * HH * HH, whhT4 + 3 * HH * HH, hf,
                                         f1, r1, HH, nullptr, nullptr, 0);

    // 8: classifier + maxpool
    dim3 cg(BB, (TN + CTT - 1) / CTT);
    cls_kernel<<<cg, 256>>>(f1, r1, bx, hf, wl1T, pooled);
    // 9: head + b_y passthrough
    out_kernel<<<BB, 128>>>(pooled, wl2, bl2, by, outb, out_size);
}

// round 16
// speedup vs baseline: 2.1412x; 1.0046x over previous
#include <cuda_runtime.h>
#include <cuda_bf16.h>
#include <math.h>
#include <cstdint>

// Problem dims
#define BB 512
#define TN 300
#define DD 200
#define HH 128
#define GG 512   // 4*H
#define MM (TN*BB)      // 153600 rows
#define KP 256          // padded K per segment

// ---------------- static device scratch ----------------
__device__ float g_xpA[(size_t)TN * BB * GG];
__device__ float g_xpB[(size_t)TN * BB * GG];
__device__ float g_f1 [(size_t)TN * BB * HH];
__device__ float g_r1 [(size_t)TN * BB * HH];
__device__ float4 g_whhT4[4 * HH * HH];          // [mat][k][h] -> (g0,g1,g2,g3)
__device__ float g_wl1T[456 * HH];
__device__ float g_pooled[BB * HH];
__device__ __nv_bfloat16 g_Ahi[(size_t)MM * KP];
__device__ __nv_bfloat16 g_Alo[(size_t)MM * KP];
__device__ __nv_bfloat16 g_W[4 * 2 * GG * KP];   // [proj][hi/lo][512][256]

__device__ __forceinline__ void atomicMaxF(float* addr, float v) {
    if (v >= 0.f) atomicMax((int*)addr, __float_as_int(v));
    else          atomicMin((unsigned int*)addr, __float_as_uint(v));
}

// ================= PTX helpers =================
__device__ __forceinline__ uint32_t smem_u32(const void* p) {
    uint32_t addr;
    asm("{ .reg .u64 tmp; cvta.to.shared.u64 tmp, %1; cvt.u32.u64 %0, tmp; }"
        : "=r"(addr) : "l"(p));
    return addr;
}
#define CP_ASYNC16(dst, src) \
    asm volatile("cp.async.ca.shared.global [%0], [%1], 16;" :: "r"(dst), "l"(src))
#define CP_COMMIT() asm volatile("cp.async.commit_group;" ::: "memory")
#define CP_WAIT1()  asm volatile("cp.async.wait_group 1;" ::: "memory")
#define CP_WAIT0()  asm volatile("cp.async.wait_group 0;" ::: "memory")

__device__ __forceinline__ void ldsm_x4(uint32_t& r0, uint32_t& r1, uint32_t& r2, uint32_t& r3,
                                        uint32_t addr) {
    asm volatile("ldmatrix.sync.aligned.m8n8.x4.shared.b16 {%0,%1,%2,%3}, [%4];"
        : "=r"(r0), "=r"(r1), "=r"(r2), "=r"(r3) : "r"(addr));
}
__device__ __forceinline__ void mma16816(float* d, const uint32_t* a, uint32_t b0, uint32_t b1) {
    asm volatile(
        "mma.sync.aligned.m16n8k16.row.col.f32.bf16.bf16.f32 "
        "{%0,%1,%2,%3}, {%4,%5,%6,%7}, {%8,%9}, {%0,%1,%2,%3};"
        : "+f"(d[0]), "+f"(d[1]), "+f"(d[2]), "+f"(d[3])
        : "r"(a[0]), "r"(a[1]), "r"(a[2]), "r"(a[3]), "r"(b0), "r"(b1));
}

// Packed fp32 pair (FFMA2) helpers
typedef unsigned long long u64t;
__device__ __forceinline__ u64t pack2(float a, float b) {
    u64t r; asm("mov.b64 %0, {%1,%2};" : "=l"(r) : "f"(a), "f"(b)); return r;
}
__device__ __forceinline__ void unpack2(u64t v, float& a, float& b) {
    asm("mov.b64 {%0,%1}, %2;" : "=f"(a), "=f"(b) : "l"(v));
}
__device__ __forceinline__ u64t fma2(u64t a, u64t b, u64t c) {
    u64t d; asm("fma.rn.f32x2 %0, %1, %2, %3;" : "=l"(d) : "l"(a), "l"(b), "l"(c)); return d;
}

// Fast activations (errors ~1e-5, budget 1e-3)
__device__ __forceinline__ float tanha(float x) {
    float y; asm("tanh.approx.f32 %0, %1;" : "=f"(y) : "f"(x)); return y;
}
// sigmoid(x) = 0.5 + 0.5*tanh(x/2): 1 MUFU instead of ex2+rcp (2 MUFU)
__device__ __forceinline__ float sigf(float x) {
    return fmaf(tanha(0.5f * x), 0.5f, 0.5f);
}

// ---------------- fused prep: whhT4, wl1T, pooled, conv_w, conv_bx (ONE launch) ----------------
__global__ void fused_prep(const float* __restrict__ wh0, const float* __restrict__ wh1,
                           const float* __restrict__ wh2, const float* __restrict__ wh3,
                           const float* __restrict__ wl1,
                           const float* __restrict__ wi0, const float* __restrict__ wi1,
                           const float* __restrict__ wi2, const float* __restrict__ wi3,
                           const float* __restrict__ bx,
                           float4* __restrict__ whhT4, float* __restrict__ wl1T,
                           float* __restrict__ pooled,
                           __nv_bfloat16* __restrict__ Wb,
                           __nv_bfloat16* __restrict__ Ahi, __nv_bfloat16* __restrict__ Alo) {
    size_t idx = (size_t)blockIdx.x * blockDim.x + threadIdx.x;
    if (idx < 4 * HH * HH) {
        int mat = (int)(idx >> 14), rem = (int)(idx & 16383);
        int k = rem >> 7, h = rem & 127;
        const float* w = (mat == 0) ? wh0 : (mat == 1) ? wh1 : (mat == 2) ? wh2 : wh3;
        whhT4[idx] = make_float4(w[(0   + h) * HH + k], w[(128 + h) * HH + k],
                                 w[(256 + h) * HH + k], w[(384 + h) * HH + k]);
    }
    if (idx < 456 * HH) {
        int f = (int)(idx >> 7), o = (int)(idx & 127);
        wl1T[idx] = wl1[o * 456 + f];
    }
    if (idx < BB * HH) pooled[idx] = -2.0f;
    if (idx < (size_t)4 * GG * KP) {
        int p = (int)(idx / (GG * KP)), rem = (int)(idx % (GG * KP));
        int n = rem >> 8, k = rem & 255;
        const float* w = (p == 0) ? wi0 : (p == 1) ? wi1 : (p == 2) ? wi2 : wi3;
        int K = (p < 2) ? DD : 2 * HH;
        float v = (k < K) ? w[(size_t)n * K + k] : 0.f;
        __nv_bfloat16 h = __float2bfloat16(v);
        Wb[(size_t)(2 * p) * GG * KP + rem] = h;
        Wb[(size_t)(2 * p + 1) * GG * KP + rem] = __float2bfloat16(v - __bfloat162float(h));
    }
    if (idx < (size_t)MM * KP) {
        int m = (int)(idx >> 8), k = (int)(idx & 255);
        int t = m >> 9, b = m & 511;
        float v = (k < DD) ? bx[(size_t)b * TN * DD + (size_t)t * DD + k] : 0.f;
        __nv_bfloat16 h = __float2bfloat16(v);
        Ahi[idx] = h;
        Alo[idx] = __float2bfloat16(v - __bfloat162float(h));
    }
}

// ---------------- HMMA projection GEMM ----------------
#define SROW 144
#define TILE_B (128 * SROW)
#define SMEM_PROJ (4 * TILE_B)
__global__ __launch_bounds__(256, 2) void proj_mma(
    const __nv_bfloat16* __restrict__ Ahi, const __nv_bfloat16* __restrict__ Alo,
    const __nv_bfloat16* __restrict__ Whi, const __nv_bfloat16* __restrict__ Wlo,
    const float* __restrict__ b1, const float* __restrict__ b2,
    float* __restrict__ C) {
    extern __shared__ __align__(16) unsigned char dsm[];
    __shared__ float bias[128];
    int tid = threadIdx.x, lane = tid & 31, wid = tid >> 5;
    int wm = wid & 3, wn = wid >> 2;
    int m0 = blockIdx.y * 128, n0 = blockIdx.x * 128;
    if (tid < 128) bias[tid] = b1[n0 + tid] + b2[n0 + tid];

    uint32_t sa0 = smem_u32(dsm);
    uint32_t sb0 = sa0 + 2 * TILE_B;
    const __nv_bfloat16* Asegs[3] = { Ahi, Ahi, Alo };
    const __nv_bfloat16* Wsegs[3] = { Whi, Wlo, Whi };
    const int total = 12;

    auto load_chunk = [&](int c, int buf) {
        int seg = c >> 2;
        int ko = (c & 3) * 64;
        const __nv_bfloat16* As = Asegs[seg] + (size_t)m0 * KP + ko;
        const __nv_bfloat16* Ws = Wsegs[seg] + (size_t)n0 * KP + ko;
#pragma unroll
        for (int i = 0; i < 4; i++) {
            int idx = tid + i * 256;
            int row = idx >> 3, w = idx & 7;
            CP_ASYNC16(sa0 + buf * TILE_B + row * SROW + w * 16,
                       As + (size_t)row * KP + w * 8);
            CP_ASYNC16(sb0 + buf * TILE_B + row * SROW + w * 16,
                       Ws + (size_t)row * KP + w * 8);
        }
        CP_COMMIT();
    };

    float acc[2][8][4] = {};
    load_chunk(0, 0);
    load_chunk(1, 1);

    for (int c = 0; c < total; c++) {
        int buf = c & 1;
        if (c + 1 < total) CP_WAIT1(); else CP_WAIT0();
        __syncthreads();
        uint32_t ab = sa0 + buf * TILE_B;
        uint32_t bb = sb0 + buf * TILE_B;
#pragma unroll
        for (int ks = 0; ks < 4; ks++) {
            uint32_t a[2][4], b[4][4];
#pragma unroll
            for (int mt = 0; mt < 2; mt++) {
                uint32_t addr = ab + (uint32_t)(wm * 32 + mt * 16 + (lane & 15)) * SROW
                                   + (uint32_t)(ks * 16 + ((lane & 16) ? 8 : 0)) * 2;
                ldsm_x4(a[mt][0], a[mt][1], a[mt][2], a[mt][3], addr);
            }
#pragma unroll
            for (int np = 0; np < 4; np++) {
                uint32_t addr = bb + (uint32_t)(wn * 64 + np * 16 + (lane & 7) + ((lane & 16) ? 8 : 0)) * SROW
                                   + (uint32_t)(ks * 16 + ((lane & 8) ? 8 : 0)) * 2;
                ldsm_x4(b[np][0], b[np][1], b[np][2], b[np][3], addr);
            }
#pragma unroll
            for (int mt = 0; mt < 2; mt++)
#pragma unroll
                for (int nt = 0; nt < 8; nt++)
                    mma16816(acc[mt][nt], a[mt], b[nt >> 1][(nt & 1) * 2],
                             b[nt >> 1][(nt & 1) * 2 + 1]);
        }
        __syncthreads();
        if (c + 2 < total) load_chunk(c + 2, buf);
    }

#pragma unroll
    for (int mt = 0; mt < 2; mt++)
#pragma unroll
        for (int nt = 0; nt < 8; nt++) {
            int row  = m0 + wm * 32 + mt * 16 + (lane >> 2);
            int colL = wn * 64 + nt * 8 + (lane & 3) * 2;
            int col  = n0 + colL;
            float2 v0 = { acc[mt][nt][0] + bias[colL], acc[mt][nt][1] + bias[colL + 1] };
            float2 v1 = { acc[mt][nt][2] + bias[colL], acc[mt][nt][3] + bias[colL + 1] };
            *(float2*)(C + (size_t)row * 512 + col) = v0;
            *(float2*)(C + (size_t)(row + 8) * 512 + col) = v1;
        }
}

// ---------------- fused bidirectional LSTM recurrence ----------------
// 256 threads: hcol = tid&127, rh = tid>>7, 4 rows each, full k per thread.
// Weights for k<KS cached in smem PRE-PACKED as u64 gate-pairs:
//   wsh2[k*256 + hcol] = {g0,g1},  wsh2[k*256 + 128 + hcol] = {g2,g3}
// k>=KS tail streamed from global with rolling depth-7 prefetch.
// h stored k-major packed {h,h} with pad-10 rows. Approx activations.
// mode 1 writes bf16 hi/lo split directly (layer-0 -> layer-1 input).
#define HPAD 10
#define KS 100
#define KT (128 - KS)   // 28 tail k-values
#define LSTM_WSM (KS * 2 * HH * sizeof(u64t))               // 204800
#define LSTM_SMEM (LSTM_WSM + 2 * HH * HPAD * sizeof(u64t)) // +20480 = 225280
__global__ __launch_bounds__(256) void lstm_kernel(
    const float* __restrict__ xpF, const float* __restrict__ xpB,
    const float4* __restrict__ whhT4F, const float4* __restrict__ whhT4B,
    const float* __restrict__ hf,
    float* __restrict__ outF, float* __restrict__ outB, int outStride,
    __nv_bfloat16* __restrict__ ohi, __nv_bfloat16* __restrict__ olo, int mode) {
    extern __shared__ __align__(16) unsigned char lsm[];
    u64t* wsh2 = (u64t*)lsm;                          // [KS][2][HH] packed gate pairs
    u64t* hshp = (u64t*)(lsm + LSTM_WSM);             // [2][HH(k)][HPAD(row)] packed {h,h}
    int dir = blockIdx.x & 1;
    int rb = (blockIdx.x >> 1) * 8;
    const float*  xp  = dir ? xpB    : xpF;
    const float4* wT4 = dir ? whhT4B : whhT4F;
    float*        out = dir ? outB   : outF;
    int tid = threadIdx.x;
    int hcol = tid & 127;
    int rh = tid >> 7;          // 0..1
    int r0 = rh * 4;

    // one-time: cache k<KS weights in smem, pre-packed as u64 pairs
    for (int i = tid; i < KS * HH; i += 256) {
        int k = i >> 7, h = i & 127;
        float4 w4 = wT4[i];
        wsh2[k * 256 + h]       = pack2(w4.x, w4.y);
        wsh2[k * 256 + 128 + h] = pack2(w4.z, w4.w);
    }

    float hfv = hf[hcol];
    float c[4];
#pragma unroll
    for (int r = 0; r < 4; r++) c[r] = hfv;
    if (rh == 0) {
        u64t hp = pack2(hfv, hfv);
#pragma unroll
        for (int r = 0; r < 8; r++) hshp[(size_t)hcol * HPAD + r] = hp;
    }
    __syncthreads();

    const float4* wpg = wT4 + (size_t)KS * HH + hcol;

    for (int t = 0; t < TN; t++) {
        int tef = dir ? (TN - 1 - t) : t;
        int cur = t & 1;
        const u64t* hcur = hshp + (size_t)cur * HH * HPAD;

        // xp loads early — latency hidden under the k-loop
        float xr[4][4];
        size_t rowbase = ((size_t)tef * BB + rb + r0) * GG + hcol;
#pragma unroll
        for (int r = 0; r < 4; r++) {
            const float* p = xp + rowbase + (size_t)r * GG;
            xr[r][0] = p[0];   xr[r][1] = p[128];
            xr[r][2] = p[256]; xr[r][3] = p[384];
        }

        // prefetch first global tail chunk before the smem bulk
        float4 wc[7];
#pragma unroll
        for (int j = 0; j < 7; j++) wc[j] = wpg[(size_t)j * HH];

        u64t a01[4] = {0ull, 0ull, 0ull, 0ull};
        u64t a23[4] = {0ull, 0ull, 0ull, 0ull};

        // ---- smem bulk: k in [0,KS) ----
#pragma unroll 10
        for (int k = 0; k < KS; k++) {
            u64t w01 = wsh2[k * 256 + hcol];
            u64t w23 = wsh2[k * 256 + 128 + hcol];
            const u64t* hp = hcur + k * HPAD + r0;
            ulonglong2 ha = *(const ulonglong2*)hp;
            ulonglong2 hb = *(const ulonglong2*)(hp + 2);
            a01[0] = fma2(ha.x, w01, a01[0]); a23[0] = fma2(ha.x, w23, a23[0]);
            a01[1] = fma2(ha.y, w01, a01[1]); a23[1] = fma2(ha.y, w23, a23[1]);
            a01[2] = fma2(hb.x, w01, a01[2]); a23[2] = fma2(hb.x, w23, a23[2]);
            a01[3] = fma2(hb.y, w01, a01[3]); a23[3] = fma2(hb.y, w23, a23[3]);
        }

        // ---- global tail: k in [KS,128), rolling depth-7 prefetch (28 = 4x7) ----
#pragma unroll
        for (int kc = 0; kc < KT; kc += 7) {
            float4 wn[7];
            if (kc + 7 < KT) {
#pragma unroll
                for (int j = 0; j < 7; j++) wn[j] = wpg[(size_t)(kc + 7 + j) * HH];
            }
#pragma unroll
            for (int j = 0; j < 7; j++) {
                int k = KS + kc + j;
                const u64t* hp = hcur + k * HPAD + r0;
                ulonglong2 ha = *(const ulonglong2*)hp;
                ulonglong2 hb = *(const ulonglong2*)(hp + 2);
                u64t w01 = pack2(wc[j].x, wc[j].y);
                u64t w23 = pack2(wc[j].z, wc[j].w);
                a01[0] = fma2(ha.x, w01, a01[0]); a23[0] = fma2(ha.x, w23, a23[0]);
                a01[1] = fma2(ha.y, w01, a01[1]); a23[1] = fma2(ha.y, w23, a23[1]);
                a01[2] = fma2(hb.x, w01, a01[2]); a23[2] = fma2(hb.x, w23, a23[2]);
                a01[3] = fma2(hb.y, w01, a01[3]); a23[3] = fma2(hb.y, w23, a23[3]);
            }
            if (kc + 7 < KT) {
#pragma unroll
                for (int j = 0; j < 7; j++) wc[j] = wn[j];
            }
        }

        // ---- epilogue: gates, state update, h write ----
        u64t* hw = hshp + ((size_t)(cur ^ 1) * HH + hcol) * HPAD + r0;
        u64t hnew[4];
#pragma unroll
        for (int r = 0; r < 4; r++) {
            float gi, gf_, gc, go;
            unpack2(a01[r], gi, gf_);
            unpack2(a23[r], gc, go);
            gi  += xr[r][0]; gf_ += xr[r][1];
            gc  += xr[r][2]; go  += xr[r][3];
            float ig = sigf(gi), fg = sigf(gf_);
            float cc = tanha(gc), og = sigf(go);
            float cv = fg * c[r] + ig * cc;
            c[r] = cv;
            float hv = og * tanha(cv);
            hnew[r] = pack2(hv, hv);
            size_t row = (size_t)tef * BB + rb + r0 + r;
            if (mode == 0) {
                out[row * outStride + hcol] = hv;
            } else {
                size_t o = row * KP + dir * 128 + hcol;
                __nv_bfloat16 hh = __float2bfloat16(hv);
                ohi[o] = hh;
                olo[o] = __float2bfloat16(hv - __bfloat162float(hh));
            }
        }
        ulonglong2 s0; s0.x = hnew[0]; s0.y = hnew[1];
        ulonglong2 s1; s1.x = hnew[2]; s1.y = hnew[3];
        *(ulonglong2*)hw = s0;
        *(ulonglong2*)(hw + 2) = s1;
        __syncthreads();
    }
}

// ---------------- classifier: h = tanh(data @ w_l1^T), max over t ----------------
#define CTT 16
__global__ __launch_bounds__(256) void cls_kernel(
    const float* __restrict__ f1, const float* __restrict__ r1,
    const float* __restrict__ bx, const float* __restrict__ hf,
    const float* __restrict__ wl1T, float* __restrict__ pooled) {
    __shared__ float ds[CTT][456];
    int b = blockIdx.x;
    int tile = blockIdx.y;
    int tid = threadIdx.x;
    for (int idx = tid; idx < CTT * 456; idx += 256) {
        int tt = idx / 456, f = idx % 456;
        int t = tile * CTT + tt;
        float v = 0.f;
        if (t < TN) {
            if (f < 128) {
                v = (t == 0) ? hf[f] : f1[((size_t)t * BB + b) * HH + f];
            } else if (f < 328) {
                v = bx[(size_t)b * TN * DD + (size_t)t * DD + (f - 128)];
            } else {
                int j = f - 328;
                v = (t == TN - 1) ? hf[j] : r1[((size_t)(TN - 2 - t) * BB + b) * HH + j];
            }
        }
        ds[tt][f] = v;
    }
    __syncthreads();

    int o2 = (tid & 63) * 2;
    int tsub = tid >> 6;
    float acc[4][2];
#pragma unroll
    for (int q = 0; q < 4; q++) { acc[q][0] = 0.f; acc[q][1] = 0.f; }
    for (int f = 0; f < 456; f++) {
        float2 w = *(const float2*)(wl1T + f * HH + o2);
#pragma unroll
        for (int q = 0; q < 4; q++) {
            float dv = ds[tsub + q * 4][f];
            acc[q][0] += dv * w.x;
            acc[q][1] += dv * w.y;
        }
    }
    float m0v = -2.f, m1v = -2.f;
#pragma unroll
    for (int q = 0; q < 4; q++) {
        int t = tile * CTT + tsub + q * 4;
        if (t < TN) {
            m0v = fmaxf(m0v, tanha(acc[q][0]));
            m1v = fmaxf(m1v, tanha(acc[q][1]));
        }
    }
    atomicMaxF(&pooled[b * HH + o2],     m0v);
    atomicMaxF(&pooled[b * HH + o2 + 1], m1v);
}

// ---------------- final head ----------------
__global__ void out_kernel(const float* __restrict__ pooled,
                           const float* __restrict__ wl2, const float* __restrict__ bl2,
                           const int* __restrict__ by, float* __restrict__ outb,
                           int out_size) {
    __shared__ float sh[128];
    int b = blockIdx.x, tid = threadIdx.x;
    float p = pooled[b * 128 + tid];
    for (int o = 0; o < 4; o++) {
        float v = p * wl2[o * 128 + tid];
        sh[tid] = v;
        __syncthreads();
        if (tid < 64) sh[tid] += sh[tid + 64];
        __syncthreads();
        if (tid < 32) {
            float s = sh[tid] + sh[tid + 32];
            for (int off = 16; off; off >>= 1) s += __shfl_down_sync(0xffffffffu, s, off);
            if (tid == 0) outb[b * 4 + o] = s + bl2[o];
        }
        __syncthreads();
    }
    if (tid == 0 && out_size >= BB * 4 + BB) outb[BB * 4 + b] = (float)by[b];
}

// ---------------- launch ----------------
extern "C" void kernel_launch(void* const* d_in, const int* in_sizes, int n_in,
                              void* d_out, int out_size) {
    const float* bx       = (const float*)d_in[0];
    const int*   by       = (const int*)  d_in[1];
    const float* hf       = (const float*)d_in[2];
    const float* w_ih[4]  = { (const float*)d_in[3],  (const float*)d_in[7],
                              (const float*)d_in[11], (const float*)d_in[15] };
    const float* w_hh[4]  = { (const float*)d_in[4],  (const float*)d_in[8],
                              (const float*)d_in[12], (const float*)d_in[16] };
    const float* b_ih[4]  = { (const float*)d_in[5],  (const float*)d_in[9],
                              (const float*)d_in[13], (const float*)d_in[17] };
    const float* b_hh[4]  = { (const float*)d_in[6],  (const float*)d_in[10],
                              (const float*)d_in[14], (const float*)d_in[18] };
    const float* wl1      = (const float*)d_in[19];
    const float* wl2      = (const float*)d_in[20];
    const float* bl2      = (const float*)d_in[21];
    float* outb = (float*)d_out;

    float *xpA, *xpB, *f1, *r1, *wl1T, *pooled;
    float4* whhT4;
    __nv_bfloat16 *Ahi, *Alo, *Wb;
    cudaGetSymbolAddress((void**)&xpA,    g_xpA);
    cudaGetSymbolAddress((void**)&xpB,    g_xpB);
    cudaGetSymbolAddress((void**)&f1,     g_f1);
    cudaGetSymbolAddress((void**)&r1,     g_r1);
    cudaGetSymbolAddress((void**)&whhT4,  g_whhT4);
    cudaGetSymbolAddress((void**)&wl1T,   g_wl1T);
    cudaGetSymbolAddress((void**)&pooled, g_pooled);
    cudaGetSymbolAddress((void**)&Ahi,    g_Ahi);
    cudaGetSymbolAddress((void**)&Alo,    g_Alo);
    cudaGetSymbolAddress((void**)&Wb,     g_W);

    cudaFuncSetAttribute(proj_mma, cudaFuncAttributeMaxDynamicSharedMemorySize, SMEM_PROJ);
    cudaFuncSetAttribute(lstm_kernel, cudaFuncAttributeMaxDynamicSharedMemorySize, LSTM_SMEM);

    dim3 pg(GG / 128, MM / 128);  // (4, 1200)

    // 0: all prep/conversions in ONE launch
    fused_prep<<<(int)(((size_t)MM * KP + 255) / 256), 256>>>(
        w_hh[0], w_hh[1], w_hh[2], w_hh[3], wl1,
        w_ih[0], w_ih[1], w_ih[2], w_ih[3], bx,
        whhT4, wl1T, pooled, Wb, Ahi, Alo);

    // 1,2: layer-0 projections
    proj_mma<<<pg, 256, SMEM_PROJ>>>(Ahi, Alo, Wb, Wb + (size_t)GG * KP,
                                     b_ih[0], b_hh[0], xpA);
    proj_mma<<<pg, 256, SMEM_PROJ>>>(Ahi, Alo, Wb + (size_t)2 * GG * KP, Wb + (size_t)3 * GG * KP,
                                     b_ih[1], b_hh[1], xpB);
    // 3: layer-0 recurrence (ncu sample slot = my launch idx 3 — verified R15)
    //    writes bf16 hi/lo split directly into Ahi/Alo (mode 1)
    lstm_kernel<<<128, 256, LSTM_SMEM>>>(xpA, xpB, whhT4, whhT4 + HH * HH, hf,
                                         nullptr, nullptr, 0, Ahi, Alo, 1);

    // 4,5: layer-1 projections
    proj_mma<<<pg, 256, SMEM_PROJ>>>(Ahi, Alo, Wb + (size_t)4 * GG * KP, Wb + (size_t)5 * GG * KP,
                                     b_ih[2], b_hh[2], xpA);
    proj_mma<<<pg, 256, SMEM_PROJ>>>(Ahi, Alo, Wb + (size_t)6 * GG * KP, Wb + (size_t)7 * GG * KP,
                                     b_ih[3], b_hh[3], xpB);
    // 6: layer-1 recurrence -> f1, r1 (mode 0)
    lstm_kernel<<<128, 256, LSTM_SMEM>>>(xpA, xpB, whhT4 + 2 * HH * HH, whhT4 + 3 * HH * HH, hf,
                                         f1, r1, HH, nullptr, nullptr, 0);

    // 7: classifier + maxpool
    dim3 cg(BB, (TN + CTT - 1) / CTT);
    cls_kernel<<<cg, 256>>>(f1, r1, bx, hf, wl1T, pooled);
    // 8: head + b_y passthrough
    out_kernel<<<BB, 128>>>(pooled, wl2, bl2, by, outb, out_size);
}